// round 11
// baseline (speedup 1.0000x reference)
#include <cuda_runtime.h>
#include <cuda_bf16.h>
#include <cstdint>

// ---------------------------------------------------------------------------
// GPT-2 attention block, all-tensor-core (mma.sync bf16 hi/lo fp32 emulation).
//   split  : x -> bf16 hi/lo  (once)
//   qkv    = x @ w_attn + b_attn  (3-pass hi/lo mma GEMM; emits q/k/v hi/lo)
//   att    = causal flash attention (3-pass mma; emits att hi/lo)
//   out    = att @ w_proj + b_proj (3-pass hi/lo mma GEMM, fp32 out)
// Attention: register diet (Q frags + P frags de-materialized) -> 2 CTAs/SM.
// ---------------------------------------------------------------------------

#define BATCH  4
#define SEQ    2048
#define DMODEL 1024
#define NHEAD  16
#define HDIM   64
#define MTOT   (BATCH * SEQ)
#define GK     1024

__device__ __nv_bfloat16 g_x_hi[(size_t)MTOT * DMODEL];
__device__ __nv_bfloat16 g_x_lo[(size_t)MTOT * DMODEL];
__device__ __nv_bfloat16 g_ao_hi[(size_t)MTOT * DMODEL];
__device__ __nv_bfloat16 g_ao_lo[(size_t)MTOT * DMODEL];
__device__ __nv_bfloat16 g_wa_hi[3 * DMODEL * DMODEL];
__device__ __nv_bfloat16 g_wa_lo[3 * DMODEL * DMODEL];
__device__ __nv_bfloat16 g_wp_hi[DMODEL * DMODEL];
__device__ __nv_bfloat16 g_wp_lo[DMODEL * DMODEL];
#define QKV_ELEMS ((size_t)NHEAD * BATCH * SEQ * HDIM)
__device__ __nv_bfloat16 g_q_hi[QKV_ELEMS];
__device__ __nv_bfloat16 g_q_lo[QKV_ELEMS];
__device__ __nv_bfloat16 g_k_hi[QKV_ELEMS];
__device__ __nv_bfloat16 g_k_lo[QKV_ELEMS];
__device__ __nv_bfloat16 g_v_hi[QKV_ELEMS];
__device__ __nv_bfloat16 g_v_lo[QKV_ELEMS];

// ---------------------------------------------------------------------------
__device__ __forceinline__ uint32_t smem_to_u32(const void* p) {
    uint32_t a;
    asm("{ .reg .u64 t; cvta.to.shared.u64 t, %1; cvt.u32.u64 %0, t; }"
        : "=r"(a) : "l"(p));
    return a;
}
__device__ __forceinline__ void ldsm_x4(uint32_t& r0, uint32_t& r1,
                                        uint32_t& r2, uint32_t& r3, uint32_t a) {
    asm volatile("ldmatrix.sync.aligned.m8n8.x4.shared.b16 {%0,%1,%2,%3}, [%4];"
                 : "=r"(r0), "=r"(r1), "=r"(r2), "=r"(r3) : "r"(a));
}
__device__ __forceinline__ void ldsm_x4_t(uint32_t& r0, uint32_t& r1,
                                          uint32_t& r2, uint32_t& r3, uint32_t a) {
    asm volatile("ldmatrix.sync.aligned.m8n8.x4.trans.shared.b16 {%0,%1,%2,%3}, [%4];"
                 : "=r"(r0), "=r"(r1), "=r"(r2), "=r"(r3) : "r"(a));
}
__device__ __forceinline__ void mma16816(float* d, const uint32_t* a,
                                         uint32_t b0, uint32_t b1) {
    asm volatile(
        "mma.sync.aligned.m16n8k16.row.col.f32.bf16.bf16.f32 "
        "{%0,%1,%2,%3}, {%4,%5,%6,%7}, {%8,%9}, {%0,%1,%2,%3};"
        : "+f"(d[0]), "+f"(d[1]), "+f"(d[2]), "+f"(d[3])
        : "r"(a[0]), "r"(a[1]), "r"(a[2]), "r"(a[3]), "r"(b0), "r"(b1));
}
#define CP_ASYNC16(dst, src) \
    asm volatile("cp.async.cg.shared.global [%0], [%1], 16;" :: "r"(dst), "l"(src) : "memory")
#define CP_COMMIT() asm volatile("cp.async.commit_group;" ::: "memory")
#define CP_WAIT0()  asm volatile("cp.async.wait_group 0;" ::: "memory")

__device__ __forceinline__ void hilo2(float x, float y, uint32_t& hi, uint32_t& lo) {
    __nv_bfloat162 h = __floats2bfloat162_rn(x, y);
    hi = *(uint32_t*)&h;
    float hx = __bfloat162float(h.x), hy = __bfloat162float(h.y);
    __nv_bfloat162 l = __floats2bfloat162_rn(x - hx, y - hy);
    lo = *(uint32_t*)&l;
}

// ---------------------------------------------------------------------------
__global__ __launch_bounds__(256)
void split_x(const float* __restrict__ x)
{
    const size_t i = ((size_t)blockIdx.x * 256 + threadIdx.x) * 4;
    float4 v = *(const float4*)(x + i);
    uint32_t h01, l01, h23, l23;
    hilo2(v.x, v.y, h01, l01);
    hilo2(v.z, v.w, h23, l23);
    *(uint2*)&g_x_hi[i] = make_uint2(h01, h23);
    *(uint2*)&g_x_lo[i] = make_uint2(l01, l23);
}

__device__ __forceinline__ void transpose_split_body(
    const float* __restrict__ w, __nv_bfloat16* __restrict__ hi,
    __nv_bfloat16* __restrict__ lo, int K, int N)
{
    __shared__ float t[32][33];
    const int n0 = blockIdx.x * 32, k0 = blockIdx.y * 32;
    const int tx = threadIdx.x, ty = threadIdx.y;
    #pragma unroll
    for (int i = ty; i < 32; i += 8)
        t[i][tx] = w[(size_t)(k0 + i) * N + n0 + tx];
    __syncthreads();
    #pragma unroll
    for (int i = ty; i < 32; i += 8) {
        float v = t[tx][i];
        __nv_bfloat16 h = __float2bfloat16(v);
        size_t idx = (size_t)(n0 + i) * K + k0 + tx;
        hi[idx] = h;
        lo[idx] = __float2bfloat16(v - __bfloat162float(h));
    }
}
__global__ void trans_wa(const float* __restrict__ w) {
    transpose_split_body(w, g_wa_hi, g_wa_lo, DMODEL, 3 * DMODEL);
}
__global__ void trans_wp(const float* __restrict__ w) {
    transpose_split_body(w, g_wp_hi, g_wp_lo, DMODEL, DMODEL);
}

// ---------------------------------------------------------------------------
// mma.sync GEMM (round-10 best): CTA 128x128, K-step 32, warp 32x64,
// 2-stage double buffer, 2 CTAs/SM, 1 sync/iter, pass-major.
// ---------------------------------------------------------------------------
#define TK      32
#define NSTEP   (GK / TK)
#define ROWB    80
#define TILEB   (128 * ROWB)      // 10240
#define STAGEB  (4 * TILEB)       // 40960: Ah, Al, Bh, Bl
#define GSMEM   (2 * STAGEB)      // 81920 -> 2 CTAs/SM

template <int MODE>
__device__ __forceinline__ void gemm_mma_body(
    const __nv_bfloat16* __restrict__ Ah, const __nv_bfloat16* __restrict__ Al,
    const __nv_bfloat16* __restrict__ BTh, const __nv_bfloat16* __restrict__ BTl,
    const float* __restrict__ bias, float* __restrict__ C, int N)
{
    extern __shared__ char smem[];
    const uint32_t sb = smem_to_u32(smem);
    const int tid  = threadIdx.x;
    const int wid  = tid >> 5;
    const int lane = tid & 31;
    const int wm   = wid & 3;
    const int wn   = wid >> 2;
    const int gid  = lane >> 2;
    const int tig  = lane & 3;
    const int m0   = blockIdx.y * 128;
    const int n0   = blockIdx.x * 128;

    float d[2][8][4];
    #pragma unroll
    for (int mt = 0; mt < 2; mt++)
        #pragma unroll
        for (int nt = 0; nt < 8; nt++)
            #pragma unroll
            for (int c = 0; c < 4; c++) d[mt][nt][c] = 0.0f;

    const uint32_t a_off = (uint32_t)((wm * 32 + (lane & 7) + ((lane >> 3) & 1) * 8) * ROWB
                                      + (lane >> 4) * 16);
    const uint32_t b_off = (uint32_t)((wn * 64 + ((lane >> 4) & 1) * 8 + (lane & 7)) * ROWB
                                      + ((lane >> 3) & 1) * 16);

    const int lrow = tid >> 1;
    const int lc   = (tid & 1) * 2;
    auto load_stage = [&](int t, int s) {
        const int k0 = t * TK;
        const uint32_t sbase = sb + s * STAGEB;
        const size_t ga = (size_t)(m0 + lrow) * GK + k0 + lc * 8;
        const size_t gb = (size_t)(n0 + lrow) * GK + k0 + lc * 8;
        const uint32_t so = (uint32_t)(lrow * ROWB + lc * 16);
        CP_ASYNC16(sbase + so,                  Ah  + ga);
        CP_ASYNC16(sbase + so + 16,             Ah  + ga + 8);
        CP_ASYNC16(sbase + TILEB + so,          Al  + ga);
        CP_ASYNC16(sbase + TILEB + so + 16,     Al  + ga + 8);
        CP_ASYNC16(sbase + 2 * TILEB + so,      BTh + gb);
        CP_ASYNC16(sbase + 2 * TILEB + so + 16, BTh + gb + 8);
        CP_ASYNC16(sbase + 3 * TILEB + so,      BTl + gb);
        CP_ASYNC16(sbase + 3 * TILEB + so + 16, BTl + gb + 8);
        CP_COMMIT();
    };

    load_stage(0, 0);

    #pragma unroll 1
    for (int t = 0; t < NSTEP; t++) {
        const int b = t & 1;
        CP_WAIT0();
        __syncthreads();
        if (t + 1 < NSTEP) load_stage(t + 1, b ^ 1);

        const uint32_t ah_base = sb + b * STAGEB + a_off;
        const uint32_t al_base = ah_base + TILEB;
        const uint32_t bh_base = sb + b * STAGEB + 2 * TILEB + b_off;
        const uint32_t bl_base = bh_base + TILEB;

        #pragma unroll
        for (int kk = 0; kk < 2; kk++) {
            const uint32_t ko = kk * 32;
            uint32_t Af[2][4], Alf[2][4];
            ldsm_x4(Af[0][0], Af[0][1], Af[0][2], Af[0][3], ah_base + ko);
            ldsm_x4(Af[1][0], Af[1][1], Af[1][2], Af[1][3], ah_base + 16 * ROWB + ko);
            ldsm_x4(Alf[0][0], Alf[0][1], Alf[0][2], Alf[0][3], al_base + ko);
            ldsm_x4(Alf[1][0], Alf[1][1], Alf[1][2], Alf[1][3], al_base + 16 * ROWB + ko);

            uint32_t Bh[8][2], Bl[8][2];
            #pragma unroll
            for (int p = 0; p < 4; p++) {
                ldsm_x4(Bh[2 * p][0], Bh[2 * p][1], Bh[2 * p + 1][0], Bh[2 * p + 1][1],
                        bh_base + p * 16 * ROWB + ko);
                ldsm_x4(Bl[2 * p][0], Bl[2 * p][1], Bl[2 * p + 1][0], Bl[2 * p + 1][1],
                        bl_base + p * 16 * ROWB + ko);
            }
            #pragma unroll
            for (int mt = 0; mt < 2; mt++)
                #pragma unroll
                for (int nt = 0; nt < 8; nt++)
                    mma16816(d[mt][nt], Af[mt], Bh[nt][0], Bh[nt][1]);
            #pragma unroll
            for (int mt = 0; mt < 2; mt++)
                #pragma unroll
                for (int nt = 0; nt < 8; nt++)
                    mma16816(d[mt][nt], Af[mt], Bl[nt][0], Bl[nt][1]);
            #pragma unroll
            for (int mt = 0; mt < 2; mt++)
                #pragma unroll
                for (int nt = 0; nt < 8; nt++)
                    mma16816(d[mt][nt], Alf[mt], Bh[nt][0], Bh[nt][1]);
        }
    }

    if (MODE == 0) {
        #pragma unroll
        for (int nt = 0; nt < 8; nt++) {
            const int col = n0 + wn * 64 + nt * 8 + tig * 2;
            const float bx = __ldg(&bias[col]);
            const float by = __ldg(&bias[col + 1]);
            #pragma unroll
            for (int mt = 0; mt < 2; mt++) {
                const size_t r0 = (size_t)(m0 + wm * 32 + mt * 16 + gid);
                *(float2*)&C[r0 * N + col] =
                    make_float2(d[mt][nt][0] + bx, d[mt][nt][1] + by);
                *(float2*)&C[(r0 + 8) * N + col] =
                    make_float2(d[mt][nt][2] + bx, d[mt][nt][3] + by);
            }
        }
    } else {
        #pragma unroll
        for (int nt = 0; nt < 8; nt++) {
            const int col = n0 + wn * 64 + nt * 8 + tig * 2;
            const float bx = __ldg(&bias[col]);
            const float by = __ldg(&bias[col + 1]);
            const int sel = col >> 10;
            const float scl = (sel == 0) ? 0.125f : 1.0f;
            __nv_bfloat16* dh = (sel == 0) ? g_q_hi : (sel == 1) ? g_k_hi : g_v_hi;
            __nv_bfloat16* dl = (sel == 0) ? g_q_lo : (sel == 1) ? g_k_lo : g_v_lo;
            const int hh = (col >> 6) & 15;
            const int dd = col & 63;
            #pragma unroll
            for (int mt = 0; mt < 2; mt++) {
                const int row = m0 + wm * 32 + mt * 16 + gid;
                const int bb = row >> 11, ss = row & 2047;
                const size_t base = ((size_t)(bb * NHEAD + hh) * SEQ + ss) * HDIM + dd;
                float v0 = (d[mt][nt][0] + bx) * scl, v1 = (d[mt][nt][1] + by) * scl;
                float v2 = (d[mt][nt][2] + bx) * scl, v3 = (d[mt][nt][3] + by) * scl;
                uint32_t h01, l01, h23, l23;
                hilo2(v0, v1, h01, l01);
                hilo2(v2, v3, h23, l23);
                *(uint32_t*)&dh[base]            = h01;
                *(uint32_t*)&dl[base]            = l01;
                *(uint32_t*)&dh[base + 8 * HDIM] = h23;
                *(uint32_t*)&dl[base + 8 * HDIM] = l23;
            }
        }
    }
}

__global__ __launch_bounds__(256, 2)
void gemm_qkv_mma(const float* __restrict__ bias)
{
    gemm_mma_body<1>(g_x_hi, g_x_lo, g_wa_hi, g_wa_lo, bias, nullptr, 3 * DMODEL);
}
__global__ __launch_bounds__(256, 2)
void gemm_proj_mma(const float* __restrict__ bias, float* __restrict__ out)
{
    gemm_mma_body<0>(g_ao_hi, g_ao_lo, g_wp_hi, g_wp_lo, bias, out, DMODEL);
}

// ---------------------------------------------------------------------------
// Causal flash attention, mma.sync bf16 hi/lo (3-pass both GEMMs).
// Register diet: Q fragments re-loaded from smem per KV tile, P fragments
// converted per-kt inside the PV loop.  <=128 regs -> 2 CTAs/SM.
// ---------------------------------------------------------------------------
#define ASTR   144
#define SQ_H   0
#define SQ_L   (128 * ASTR)
#define AKV0   (2 * 128 * ASTR)
#define KVBUF  (4 * 64 * ASTR)
#define SKV(s, t) (AKV0 + (s) * KVBUF + (t) * (64 * ASTR))
#define ATT_SMEM (AKV0 + 2 * KVBUF)      // 110592; x2 = 221184 <= 228KB/SM

__global__ __launch_bounds__(256, 2)
void attn_mma()
{
    extern __shared__ char smem[];
    const uint32_t sb = smem_to_u32(smem);
    const int tid  = threadIdx.x;
    const int wid  = tid >> 5;
    const int lane = tid & 31;
    const int g    = lane >> 2;
    const int t2   = (lane & 3) * 2;
    const int qi   = (int)(gridDim.x - 1 - blockIdx.x);  // heavy tiles first
    const int bh   = blockIdx.y;
    const int bb   = bh >> 4;
    const int h    = bh & 15;
    const int q0   = qi * 128;
    const int wm0  = wid * 16;

    const size_t head_base = (size_t)bh * SEQ * HDIM;

    auto load_kv = [&](int jt, int s) {
        #pragma unroll
        for (int tp = 0; tp < 4; tp++) {
            const __nv_bfloat16* bp =
                (tp == 0) ? g_k_hi : (tp == 1) ? g_k_lo : (tp == 2) ? g_v_hi : g_v_lo;
            #pragma unroll
            for (int j = 0; j < 2; j++) {
                int idx = tid + (tp * 2 + j) * 256;
                int row = (idx >> 3) & 63;
                int c   = idx & 7;
                uint32_t dst = sb + SKV(s, tp) + row * ASTR + c * 16;
                const __nv_bfloat16* src =
                    bp + head_base + (size_t)(jt * 64 + row) * HDIM + c * 8;
                CP_ASYNC16(dst, src);
            }
        }
        CP_COMMIT();
    };

    load_kv(0, 0);

    {
        const __nv_bfloat16* qh_g = g_q_hi + head_base + (size_t)q0 * HDIM;
        const __nv_bfloat16* ql_g = g_q_lo + head_base + (size_t)q0 * HDIM;
        #pragma unroll
        for (int i = 0; i < 4; i++) {
            int idx = tid + i * 256;
            int row = idx >> 3;
            int c   = idx & 7;
            *(uint4*)(smem + SQ_H + row * ASTR + c * 16) =
                *(const uint4*)(qh_g + (size_t)row * HDIM + c * 8);
            *(uint4*)(smem + SQ_L + row * ASTR + c * 16) =
                *(const uint4*)(ql_g + (size_t)row * HDIM + c * 8);
        }
    }
    CP_WAIT0();
    __syncthreads();

    // Q ldsm base (fragments re-loaded per KV tile; not persistent)
    const uint32_t qaddr = sb + SQ_H +
        (uint32_t)((wm0 + (lane & 7) + ((lane >> 3) & 1) * 8) * ASTR + (lane >> 4) * 16);

    float o[8][4];
    #pragma unroll
    for (int nt = 0; nt < 8; nt++)
        #pragma unroll
        for (int c = 0; c < 4; c++) o[nt][c] = 0.0f;
    float mrun0 = -1e30f, mrun1 = -1e30f, lrun0 = 0.0f, lrun1 = 0.0f;

    const int njt = 2 * qi + 2;
    const uint32_t k_off =
        (uint32_t)(((lane & 7) + ((lane >> 4) & 1) * 8) * ASTR + ((lane >> 3) & 1) * 16);
    const uint32_t v_off =
        (uint32_t)(((lane & 7) + ((lane >> 3) & 1) * 8) * ASTR + (lane >> 4) * 16);

    #pragma unroll 1
    for (int jt = 0; jt < njt; jt++) {
        const int bfr = jt & 1;
        if (jt + 1 < njt) load_kv(jt + 1, bfr ^ 1);

        float s[8][4];
        #pragma unroll
        for (int nt = 0; nt < 8; nt++)
            #pragma unroll
            for (int c = 0; c < 4; c++) s[nt][c] = 0.0f;

        const uint32_t kaddr = sb + SKV(bfr, 0) + k_off;
        #pragma unroll
        for (int kt = 0; kt < 4; kt++) {
            uint32_t qh[4], ql[4];
            ldsm_x4(qh[0], qh[1], qh[2], qh[3], qaddr + kt * 32);
            ldsm_x4(ql[0], ql[1], ql[2], ql[3], qaddr + (SQ_L - SQ_H) + kt * 32);
            #pragma unroll
            for (int np = 0; np < 4; np++) {
                uint32_t a0, a1, a2, a3, b0, b1, b2, b3;
                uint32_t base = kaddr + np * (16 * ASTR) + kt * 32;
                ldsm_x4(a0, a1, a2, a3, base);
                ldsm_x4(b0, b1, b2, b3, base + 64 * ASTR);
                mma16816(s[2 * np],     qh, a0, a1);
                mma16816(s[2 * np + 1], qh, a2, a3);
                mma16816(s[2 * np],     ql, a0, a1);
                mma16816(s[2 * np + 1], ql, a2, a3);
                mma16816(s[2 * np],     qh, b0, b1);
                mma16816(s[2 * np + 1], qh, b2, b3);
            }
        }

        if (jt * 64 + 63 > q0 + wm0) {
            const int row0 = q0 + wm0 + g;
            #pragma unroll
            for (int nt = 0; nt < 8; nt++) {
                const int col = jt * 64 + nt * 8 + t2;
                #pragma unroll
                for (int c = 0; c < 4; c++) {
                    int cc = col + (c & 1);
                    int rr = row0 + (c >> 1) * 8;
                    if (cc > rr) s[nt][c] = -1e30f;
                }
            }
        }

        float mt0 = -1e30f, mt1 = -1e30f;
        #pragma unroll
        for (int nt = 0; nt < 8; nt++) {
            mt0 = fmaxf(mt0, fmaxf(s[nt][0], s[nt][1]));
            mt1 = fmaxf(mt1, fmaxf(s[nt][2], s[nt][3]));
        }
        mt0 = fmaxf(mt0, __shfl_xor_sync(0xffffffffu, mt0, 1));
        mt0 = fmaxf(mt0, __shfl_xor_sync(0xffffffffu, mt0, 2));
        mt1 = fmaxf(mt1, __shfl_xor_sync(0xffffffffu, mt1, 1));
        mt1 = fmaxf(mt1, __shfl_xor_sync(0xffffffffu, mt1, 2));

        const float mn0 = fmaxf(mrun0, mt0);
        const float mn1 = fmaxf(mrun1, mt1);
        const float f0 = __expf(mrun0 - mn0);
        const float f1 = __expf(mrun1 - mn1);
        mrun0 = mn0; mrun1 = mn1;

        float lt0 = 0.0f, lt1 = 0.0f;
        #pragma unroll
        for (int nt = 0; nt < 8; nt++) {
            s[nt][0] = __expf(s[nt][0] - mn0); lt0 += s[nt][0];
            s[nt][1] = __expf(s[nt][1] - mn0); lt0 += s[nt][1];
            s[nt][2] = __expf(s[nt][2] - mn1); lt1 += s[nt][2];
            s[nt][3] = __expf(s[nt][3] - mn1); lt1 += s[nt][3];
        }
        lt0 += __shfl_xor_sync(0xffffffffu, lt0, 1);
        lt0 += __shfl_xor_sync(0xffffffffu, lt0, 2);
        lt1 += __shfl_xor_sync(0xffffffffu, lt1, 1);
        lt1 += __shfl_xor_sync(0xffffffffu, lt1, 2);
        lrun0 = lrun0 * f0 + lt0;
        lrun1 = lrun1 * f1 + lt1;
        #pragma unroll
        for (int nt = 0; nt < 8; nt++) {
            o[nt][0] *= f0; o[nt][1] *= f0;
            o[nt][2] *= f1; o[nt][3] *= f1;
        }

        // O += P @ V : P fragments converted per-kt (short live range)
        const uint32_t vaddr = sb + SKV(bfr, 2) + v_off;
        #pragma unroll
        for (int kt = 0; kt < 4; kt++) {
            uint32_t aph[4], apl[4];
            hilo2(s[2 * kt][0],     s[2 * kt][1],     aph[0], apl[0]);
            hilo2(s[2 * kt][2],     s[2 * kt][3],     aph[1], apl[1]);
            hilo2(s[2 * kt + 1][0], s[2 * kt + 1][1], aph[2], apl[2]);
            hilo2(s[2 * kt + 1][2], s[2 * kt + 1][3], aph[3], apl[3]);
            #pragma unroll
            for (int np = 0; np < 4; np++) {
                uint32_t v0, v1, v2, v3, w0, w1, w2, w3;
                uint32_t base = vaddr + kt * (16 * ASTR) + np * 32;
                ldsm_x4_t(v0, v1, v2, v3, base);
                ldsm_x4_t(w0, w1, w2, w3, base + 64 * ASTR);
                mma16816(o[2 * np],     aph, v0, v1);
                mma16816(o[2 * np + 1], aph, v2, v3);
                mma16816(o[2 * np],     apl, v0, v1);
                mma16816(o[2 * np + 1], apl, v2, v3);
                mma16816(o[2 * np],     aph, w0, w1);
                mma16816(o[2 * np + 1], aph, w2, w3);
            }
        }

        CP_WAIT0();
        __syncthreads();
    }

    const float inv0 = 1.0f / lrun0;
    const float inv1 = 1.0f / lrun1;
    const size_t r0 = (size_t)bb * SEQ + q0 + wm0 + g;
    const int colb = h * HDIM + t2;
    #pragma unroll
    for (int nt = 0; nt < 8; nt++) {
        uint32_t hi, lo;
        hilo2(o[nt][0] * inv0, o[nt][1] * inv0, hi, lo);
        *(uint32_t*)&g_ao_hi[r0 * DMODEL + colb + nt * 8] = hi;
        *(uint32_t*)&g_ao_lo[r0 * DMODEL + colb + nt * 8] = lo;
        hilo2(o[nt][2] * inv1, o[nt][3] * inv1, hi, lo);
        *(uint32_t*)&g_ao_hi[(r0 + 8) * DMODEL + colb + nt * 8] = hi;
        *(uint32_t*)&g_ao_lo[(r0 + 8) * DMODEL + colb + nt * 8] = lo;
    }
}

// ---------------------------------------------------------------------------
extern "C" void kernel_launch(void* const* d_in, const int* in_sizes, int n_in,
                              void* d_out, int out_size)
{
    const float* x      = (const float*)d_in[0];
    const float* w_attn = (const float*)d_in[1];
    const float* b_attn = (const float*)d_in[2];
    const float* w_proj = (const float*)d_in[3];
    const float* b_proj = (const float*)d_in[4];
    float* out = (float*)d_out;

    cudaFuncSetAttribute(attn_mma,
                         cudaFuncAttributeMaxDynamicSharedMemorySize, ATT_SMEM);
    cudaFuncSetAttribute(gemm_qkv_mma,
                         cudaFuncAttributeMaxDynamicSharedMemorySize, GSMEM);
    cudaFuncSetAttribute(gemm_proj_mma,
                         cudaFuncAttributeMaxDynamicSharedMemorySize, GSMEM);

    split_x<<<MTOT * DMODEL / 1024, 256>>>(x);
    trans_wa<<<dim3(3 * DMODEL / 32, DMODEL / 32), dim3(32, 8)>>>(w_attn);
    trans_wp<<<dim3(DMODEL / 32, DMODEL / 32), dim3(32, 8)>>>(w_proj);

    gemm_qkv_mma<<<dim3(3 * DMODEL / 128, MTOT / 128), 256, GSMEM>>>(b_attn);
    attn_mma<<<dim3(SEQ / 128, BATCH * NHEAD), 256, ATT_SMEM>>>();
    gemm_proj_mma<<<dim3(DMODEL / 128, MTOT / 128), 256, GSMEM>>>(b_proj, out);
}

// round 12
// speedup vs baseline: 1.3816x; 1.3816x over previous
#include <cuda_runtime.h>
#include <cuda_fp16.h>
#include <cstdint>

// ---------------------------------------------------------------------------
// GPT-2 attention block, all-tensor-core (mma.sync fp16 hi/lo, 2-pass).
//   A-side operands: single fp16 (residual dropped; ~1.6e-4 normwise/stage)
//   B-side operands: fp16 hi + lo (2 MMA passes)
//   split  : x -> fp16                       (once)
//   qkv    = x @ w_attn + b_attn             (emits q fp16, k/v fp16 hi/lo)
//   att    = causal flash attention          (emits att fp16)
//   out    = att @ w_proj + b_proj           (fp32 out)
// GEMM: CTA 128x128, warp 32x64, K-step 32, 2-stage, 2 CTAs/SM.
// ---------------------------------------------------------------------------

#define BATCH  4
#define SEQ    2048
#define DMODEL 1024
#define NHEAD  16
#define HDIM   64
#define MTOT   (BATCH * SEQ)
#define GK     1024

__device__ __half g_x_h[(size_t)MTOT * DMODEL];
__device__ __half g_ao_h[(size_t)MTOT * DMODEL];
__device__ __half g_wa_h[3 * DMODEL * DMODEL];
__device__ __half g_wa_l[3 * DMODEL * DMODEL];
__device__ __half g_wp_h[DMODEL * DMODEL];
__device__ __half g_wp_l[DMODEL * DMODEL];
#define QKV_ELEMS ((size_t)NHEAD * BATCH * SEQ * HDIM)
__device__ __half g_q_h[QKV_ELEMS];
__device__ __half g_k_h[QKV_ELEMS];
__device__ __half g_k_l[QKV_ELEMS];
__device__ __half g_v_h[QKV_ELEMS];
__device__ __half g_v_l[QKV_ELEMS];

// ---------------------------------------------------------------------------
__device__ __forceinline__ uint32_t smem_to_u32(const void* p) {
    uint32_t a;
    asm("{ .reg .u64 t; cvta.to.shared.u64 t, %1; cvt.u32.u64 %0, t; }"
        : "=r"(a) : "l"(p));
    return a;
}
__device__ __forceinline__ void ldsm_x4(uint32_t& r0, uint32_t& r1,
                                        uint32_t& r2, uint32_t& r3, uint32_t a) {
    asm volatile("ldmatrix.sync.aligned.m8n8.x4.shared.b16 {%0,%1,%2,%3}, [%4];"
                 : "=r"(r0), "=r"(r1), "=r"(r2), "=r"(r3) : "r"(a));
}
__device__ __forceinline__ void ldsm_x4_t(uint32_t& r0, uint32_t& r1,
                                          uint32_t& r2, uint32_t& r3, uint32_t a) {
    asm volatile("ldmatrix.sync.aligned.m8n8.x4.trans.shared.b16 {%0,%1,%2,%3}, [%4];"
                 : "=r"(r0), "=r"(r1), "=r"(r2), "=r"(r3) : "r"(a));
}
__device__ __forceinline__ void mma16816(float* d, const uint32_t* a,
                                         uint32_t b0, uint32_t b1) {
    asm volatile(
        "mma.sync.aligned.m16n8k16.row.col.f32.f16.f16.f32 "
        "{%0,%1,%2,%3}, {%4,%5,%6,%7}, {%8,%9}, {%0,%1,%2,%3};"
        : "+f"(d[0]), "+f"(d[1]), "+f"(d[2]), "+f"(d[3])
        : "r"(a[0]), "r"(a[1]), "r"(a[2]), "r"(a[3]), "r"(b0), "r"(b1));
}
#define CP_ASYNC16(dst, src) \
    asm volatile("cp.async.cg.shared.global [%0], [%1], 16;" :: "r"(dst), "l"(src) : "memory")
#define CP_COMMIT() asm volatile("cp.async.commit_group;" ::: "memory")
#define CP_WAIT0()  asm volatile("cp.async.wait_group 0;" ::: "memory")

__device__ __forceinline__ uint32_t pack_h2(float x, float y) {
    __half2 h = __floats2half2_rn(x, y);
    return *(uint32_t*)&h;
}
__device__ __forceinline__ void hilo2h(float x, float y, uint32_t& hi, uint32_t& lo) {
    __half2 h = __floats2half2_rn(x, y);
    hi = *(uint32_t*)&h;
    float hx = __low2float(h), hy = __high2float(h);
    __half2 l = __floats2half2_rn(x - hx, y - hy);
    lo = *(uint32_t*)&l;
}

// ---------------------------------------------------------------------------
__global__ __launch_bounds__(256)
void split_x(const float* __restrict__ x)
{
    const size_t i = ((size_t)blockIdx.x * 256 + threadIdx.x) * 4;
    float4 v = *(const float4*)(x + i);
    *(uint2*)&g_x_h[i] = make_uint2(pack_h2(v.x, v.y), pack_h2(v.z, v.w));
}

__device__ __forceinline__ void transpose_split_body(
    const float* __restrict__ w, __half* __restrict__ hi,
    __half* __restrict__ lo, int K, int N)
{
    __shared__ float t[32][33];
    const int n0 = blockIdx.x * 32, k0 = blockIdx.y * 32;
    const int tx = threadIdx.x, ty = threadIdx.y;
    #pragma unroll
    for (int i = ty; i < 32; i += 8)
        t[i][tx] = w[(size_t)(k0 + i) * N + n0 + tx];
    __syncthreads();
    #pragma unroll
    for (int i = ty; i < 32; i += 8) {
        float v = t[tx][i];
        __half h = __float2half(v);
        size_t idx = (size_t)(n0 + i) * K + k0 + tx;
        hi[idx] = h;
        lo[idx] = __float2half(v - __half2float(h));
    }
}
__global__ void trans_wa(const float* __restrict__ w) {
    transpose_split_body(w, g_wa_h, g_wa_l, DMODEL, 3 * DMODEL);
}
__global__ void trans_wp(const float* __restrict__ w) {
    transpose_split_body(w, g_wp_h, g_wp_l, DMODEL, DMODEL);
}

// ---------------------------------------------------------------------------
// mma.sync GEMM: C = A(fp16) @ BT(fp16 hi/lo) + bias, 2 passes.
// CTA 128x128, K-step 32, 8 warps (4 M x 2 N), warp tile 32x64.
// 2-stage double buffer, 2 CTAs/SM, 1 sync/iter, pass-major.
// ---------------------------------------------------------------------------
#define TK      32
#define NSTEP   (GK / TK)
#define ROWB    80
#define TILEB   (128 * ROWB)      // 10240
#define STAGEB  (3 * TILEB)       // 30720: A, Bh, Bl
#define GSMEM   (2 * STAGEB)      // 61440 -> 2 CTAs/SM

template <int MODE>
__device__ __forceinline__ void gemm_mma_body(
    const __half* __restrict__ A,
    const __half* __restrict__ BTh, const __half* __restrict__ BTl,
    const float* __restrict__ bias, float* __restrict__ C, int N)
{
    extern __shared__ char smem[];
    const uint32_t sb = smem_to_u32(smem);
    const int tid  = threadIdx.x;
    const int lane = tid & 31;
    const int wid  = tid >> 5;
    const int wm   = wid & 3;
    const int wn   = wid >> 2;
    const int gid  = lane >> 2;
    const int tig  = lane & 3;
    const int m0   = blockIdx.y * 128;
    const int n0   = blockIdx.x * 128;

    float d[2][8][4];
    #pragma unroll
    for (int mt = 0; mt < 2; mt++)
        #pragma unroll
        for (int nt = 0; nt < 8; nt++)
            #pragma unroll
            for (int c = 0; c < 4; c++) d[mt][nt][c] = 0.0f;

    const uint32_t a_off = (uint32_t)((wm * 32 + (lane & 7) + ((lane >> 3) & 1) * 8) * ROWB
                                      + (lane >> 4) * 16);
    const uint32_t b_off = (uint32_t)((wn * 64 + ((lane >> 4) & 1) * 8 + (lane & 7)) * ROWB
                                      + ((lane >> 3) & 1) * 16);

    const int lrow = tid >> 1;
    const int lc   = (tid & 1) * 2;
    auto load_stage = [&](int t, int s) {
        const int k0 = t * TK;
        const uint32_t sbase = sb + s * STAGEB;
        const size_t ga = (size_t)(m0 + lrow) * GK + k0 + lc * 8;
        const size_t gb = (size_t)(n0 + lrow) * GK + k0 + lc * 8;
        const uint32_t so = (uint32_t)(lrow * ROWB + lc * 16);
        CP_ASYNC16(sbase + so,                  A   + ga);
        CP_ASYNC16(sbase + so + 16,             A   + ga + 8);
        CP_ASYNC16(sbase + TILEB + so,          BTh + gb);
        CP_ASYNC16(sbase + TILEB + so + 16,     BTh + gb + 8);
        CP_ASYNC16(sbase + 2 * TILEB + so,      BTl + gb);
        CP_ASYNC16(sbase + 2 * TILEB + so + 16, BTl + gb + 8);
        CP_COMMIT();
    };

    load_stage(0, 0);

    #pragma unroll 1
    for (int t = 0; t < NSTEP; t++) {
        const int b = t & 1;
        CP_WAIT0();
        __syncthreads();
        if (t + 1 < NSTEP) load_stage(t + 1, b ^ 1);

        const uint32_t ah_base = sb + b * STAGEB + a_off;
        const uint32_t bh_base = sb + b * STAGEB + TILEB + b_off;
        const uint32_t bl_base = bh_base + TILEB;

        #pragma unroll
        for (int kk = 0; kk < 2; kk++) {
            const uint32_t ko = kk * 32;
            uint32_t Af[2][4];
            ldsm_x4(Af[0][0], Af[0][1], Af[0][2], Af[0][3], ah_base + ko);
            ldsm_x4(Af[1][0], Af[1][1], Af[1][2], Af[1][3], ah_base + 16 * ROWB + ko);

            uint32_t Bh[8][2], Bl[8][2];
            #pragma unroll
            for (int p = 0; p < 4; p++) {
                ldsm_x4(Bh[2 * p][0], Bh[2 * p][1], Bh[2 * p + 1][0], Bh[2 * p + 1][1],
                        bh_base + p * 16 * ROWB + ko);
                ldsm_x4(Bl[2 * p][0], Bl[2 * p][1], Bl[2 * p + 1][0], Bl[2 * p + 1][1],
                        bl_base + p * 16 * ROWB + ko);
            }
            // pass-major: hi then lo
            #pragma unroll
            for (int mt = 0; mt < 2; mt++)
                #pragma unroll
                for (int nt = 0; nt < 8; nt++)
                    mma16816(d[mt][nt], Af[mt], Bh[nt][0], Bh[nt][1]);
            #pragma unroll
            for (int mt = 0; mt < 2; mt++)
                #pragma unroll
                for (int nt = 0; nt < 8; nt++)
                    mma16816(d[mt][nt], Af[mt], Bl[nt][0], Bl[nt][1]);
        }
    }

    if (MODE == 0) {
        #pragma unroll
        for (int nt = 0; nt < 8; nt++) {
            const int col = n0 + wn * 64 + nt * 8 + tig * 2;
            const float bx = __ldg(&bias[col]);
            const float by = __ldg(&bias[col + 1]);
            #pragma unroll
            for (int mt = 0; mt < 2; mt++) {
                const size_t r0 = (size_t)(m0 + wm * 32 + mt * 16 + gid);
                *(float2*)&C[r0 * N + col] =
                    make_float2(d[mt][nt][0] + bx, d[mt][nt][1] + by);
                *(float2*)&C[(r0 + 8) * N + col] =
                    make_float2(d[mt][nt][2] + bx, d[mt][nt][3] + by);
            }
        }
    } else {
        // qkv epilogue: q -> fp16 (scaled 1/8), k/v -> fp16 hi/lo, head layout
        #pragma unroll
        for (int nt = 0; nt < 8; nt++) {
            const int col = n0 + wn * 64 + nt * 8 + tig * 2;
            const float bx = __ldg(&bias[col]);
            const float by = __ldg(&bias[col + 1]);
            const int sel = col >> 10;
            const float scl = (sel == 0) ? 0.125f : 1.0f;
            __half* dh = (sel == 0) ? g_q_h : (sel == 1) ? g_k_h : g_v_h;
            __half* dl = (sel == 1) ? g_k_l : g_v_l;
            const int hh = (col >> 6) & 15;
            const int dd = col & 63;
            #pragma unroll
            for (int mt = 0; mt < 2; mt++) {
                const int row = m0 + wm * 32 + mt * 16 + gid;
                const int bb = row >> 11, ss = row & 2047;
                const size_t base = ((size_t)(bb * NHEAD + hh) * SEQ + ss) * HDIM + dd;
                float v0 = (d[mt][nt][0] + bx) * scl, v1 = (d[mt][nt][1] + by) * scl;
                float v2 = (d[mt][nt][2] + bx) * scl, v3 = (d[mt][nt][3] + by) * scl;
                uint32_t h01, l01, h23, l23;
                hilo2h(v0, v1, h01, l01);
                hilo2h(v2, v3, h23, l23);
                *(uint32_t*)&dh[base]            = h01;
                *(uint32_t*)&dh[base + 8 * HDIM] = h23;
                if (sel != 0) {
                    *(uint32_t*)&dl[base]            = l01;
                    *(uint32_t*)&dl[base + 8 * HDIM] = l23;
                }
            }
        }
    }
}

__global__ __launch_bounds__(256, 2)
void gemm_qkv_mma(const float* __restrict__ bias)
{
    gemm_mma_body<1>(g_x_h, g_wa_h, g_wa_l, bias, nullptr, 3 * DMODEL);
}
__global__ __launch_bounds__(256, 2)
void gemm_proj_mma(const float* __restrict__ bias, float* __restrict__ out)
{
    gemm_mma_body<0>(g_ao_h, g_wp_h, g_wp_l, bias, out, DMODEL);
}

// ---------------------------------------------------------------------------
// Causal flash attention, fp16 2-pass (Q fp16; K,V fp16 hi/lo).
// CTA = (128 q rows, bh), 8 warps x m16, KV tile 64, double buffered.
// ---------------------------------------------------------------------------
#define ASTR   144
#define SQ_H   0
#define AKV0   (128 * ASTR)                    // 18432
#define KVBUF  (4 * 64 * ASTR)                 // 36864 (Kh,Kl,Vh,Vl)
#define SKV(s, t) (AKV0 + (s) * KVBUF + (t) * (64 * ASTR))
#define ATT_SMEM (AKV0 + 2 * KVBUF)            // 92160; x2 = 184320 fits

__global__ __launch_bounds__(256, 2)
void attn_mma()
{
    extern __shared__ char smem[];
    const uint32_t sb = smem_to_u32(smem);
    const int tid  = threadIdx.x;
    const int wid  = tid >> 5;
    const int lane = tid & 31;
    const int g    = lane >> 2;
    const int t2   = (lane & 3) * 2;
    const int qi   = (int)(gridDim.x - 1 - blockIdx.x);  // heavy tiles first
    const int bh   = blockIdx.y;
    const int bb   = bh >> 4;
    const int h    = bh & 15;
    const int q0   = qi * 128;
    const int wm0  = wid * 16;

    const size_t head_base = (size_t)bh * SEQ * HDIM;

    auto load_kv = [&](int jt, int s) {
        #pragma unroll
        for (int tp = 0; tp < 4; tp++) {
            const __half* bp =
                (tp == 0) ? g_k_h : (tp == 1) ? g_k_l : (tp == 2) ? g_v_h : g_v_l;
            #pragma unroll
            for (int j = 0; j < 2; j++) {
                int idx = tid + (tp * 2 + j) * 256;
                int row = (idx >> 3) & 63;
                int c   = idx & 7;
                uint32_t dst = sb + SKV(s, tp) + row * ASTR + c * 16;
                const __half* src =
                    bp + head_base + (size_t)(jt * 64 + row) * HDIM + c * 8;
                CP_ASYNC16(dst, src);
            }
        }
        CP_COMMIT();
    };

    load_kv(0, 0);

    {
        const __half* q_g = g_q_h + head_base + (size_t)q0 * HDIM;
        #pragma unroll
        for (int i = 0; i < 4; i++) {
            int idx = tid + i * 256;
            int row = idx >> 3;
            int c   = idx & 7;
            *(uint4*)(smem + SQ_H + row * ASTR + c * 16) =
                *(const uint4*)(q_g + (size_t)row * HDIM + c * 8);
        }
    }
    CP_WAIT0();
    __syncthreads();

    const uint32_t qaddr = sb + SQ_H +
        (uint32_t)((wm0 + (lane & 7) + ((lane >> 3) & 1) * 8) * ASTR + (lane >> 4) * 16);

    float o[8][4];
    #pragma unroll
    for (int nt = 0; nt < 8; nt++)
        #pragma unroll
        for (int c = 0; c < 4; c++) o[nt][c] = 0.0f;
    float mrun0 = -1e30f, mrun1 = -1e30f, lrun0 = 0.0f, lrun1 = 0.0f;

    const int njt = 2 * qi + 2;
    const uint32_t k_off =
        (uint32_t)(((lane & 7) + ((lane >> 4) & 1) * 8) * ASTR + ((lane >> 3) & 1) * 16);
    const uint32_t v_off =
        (uint32_t)(((lane & 7) + ((lane >> 3) & 1) * 8) * ASTR + (lane >> 4) * 16);

    #pragma unroll 1
    for (int jt = 0; jt < njt; jt++) {
        const int bfr = jt & 1;
        if (jt + 1 < njt) load_kv(jt + 1, bfr ^ 1);

        float s[8][4];
        #pragma unroll
        for (int nt = 0; nt < 8; nt++)
            #pragma unroll
            for (int c = 0; c < 4; c++) s[nt][c] = 0.0f;

        const uint32_t kaddr = sb + SKV(bfr, 0) + k_off;
        #pragma unroll
        for (int kt = 0; kt < 4; kt++) {
            uint32_t qf[4];
            ldsm_x4(qf[0], qf[1], qf[2], qf[3], qaddr + kt * 32);
            #pragma unroll
            for (int np = 0; np < 4; np++) {
                uint32_t a0, a1, a2, a3, b0, b1, b2, b3;
                uint32_t base = kaddr + np * (16 * ASTR) + kt * 32;
                ldsm_x4(a0, a1, a2, a3, base);                 // K hi
                ldsm_x4(b0, b1, b2, b3, base + 64 * ASTR);     // K lo
                mma16816(s[2 * np],     qf, a0, a1);
                mma16816(s[2 * np + 1], qf, a2, a3);
                mma16816(s[2 * np],     qf, b0, b1);
                mma16816(s[2 * np + 1], qf, b2, b3);
            }
        }

        if (jt * 64 + 63 > q0 + wm0) {
            const int row0 = q0 + wm0 + g;
            #pragma unroll
            for (int nt = 0; nt < 8; nt++) {
                const int col = jt * 64 + nt * 8 + t2;
                #pragma unroll
                for (int c = 0; c < 4; c++) {
                    int cc = col + (c & 1);
                    int rr = row0 + (c >> 1) * 8;
                    if (cc > rr) s[nt][c] = -1e30f;
                }
            }
        }

        float mt0 = -1e30f, mt1 = -1e30f;
        #pragma unroll
        for (int nt = 0; nt < 8; nt++) {
            mt0 = fmaxf(mt0, fmaxf(s[nt][0], s[nt][1]));
            mt1 = fmaxf(mt1, fmaxf(s[nt][2], s[nt][3]));
        }
        mt0 = fmaxf(mt0, __shfl_xor_sync(0xffffffffu, mt0, 1));
        mt0 = fmaxf(mt0, __shfl_xor_sync(0xffffffffu, mt0, 2));
        mt1 = fmaxf(mt1, __shfl_xor_sync(0xffffffffu, mt1, 1));
        mt1 = fmaxf(mt1, __shfl_xor_sync(0xffffffffu, mt1, 2));

        const float mn0 = fmaxf(mrun0, mt0);
        const float mn1 = fmaxf(mrun1, mt1);
        const float f0 = __expf(mrun0 - mn0);
        const float f1 = __expf(mrun1 - mn1);
        mrun0 = mn0; mrun1 = mn1;

        float lt0 = 0.0f, lt1 = 0.0f;
        #pragma unroll
        for (int nt = 0; nt < 8; nt++) {
            s[nt][0] = __expf(s[nt][0] - mn0); lt0 += s[nt][0];
            s[nt][1] = __expf(s[nt][1] - mn0); lt0 += s[nt][1];
            s[nt][2] = __expf(s[nt][2] - mn1); lt1 += s[nt][2];
            s[nt][3] = __expf(s[nt][3] - mn1); lt1 += s[nt][3];
        }
        lt0 += __shfl_xor_sync(0xffffffffu, lt0, 1);
        lt0 += __shfl_xor_sync(0xffffffffu, lt0, 2);
        lt1 += __shfl_xor_sync(0xffffffffu, lt1, 1);
        lt1 += __shfl_xor_sync(0xffffffffu, lt1, 2);
        lrun0 = lrun0 * f0 + lt0;
        lrun1 = lrun1 * f1 + lt1;
        #pragma unroll
        for (int nt = 0; nt < 8; nt++) {
            o[nt][0] *= f0; o[nt][1] *= f0;
            o[nt][2] *= f1; o[nt][3] *= f1;
        }

        // O += P @ V : P as single fp16, V hi/lo (2 passes)
        const uint32_t vaddr = sb + SKV(bfr, 2) + v_off;
        #pragma unroll
        for (int kt = 0; kt < 4; kt++) {
            uint32_t ap[4];
            ap[0] = pack_h2(s[2 * kt][0],     s[2 * kt][1]);
            ap[1] = pack_h2(s[2 * kt][2],     s[2 * kt][3]);
            ap[2] = pack_h2(s[2 * kt + 1][0], s[2 * kt + 1][1]);
            ap[3] = pack_h2(s[2 * kt + 1][2], s[2 * kt + 1][3]);
            #pragma unroll
            for (int np = 0; np < 4; np++) {
                uint32_t v0, v1, v2, v3, w0, w1, w2, w3;
                uint32_t base = vaddr + kt * (16 * ASTR) + np * 32;
                ldsm_x4_t(v0, v1, v2, v3, base);               // V hi
                ldsm_x4_t(w0, w1, w2, w3, base + 64 * ASTR);   // V lo
                mma16816(o[2 * np],     ap, v0, v1);
                mma16816(o[2 * np + 1], ap, v2, v3);
                mma16816(o[2 * np],     ap, w0, w1);
                mma16816(o[2 * np + 1], ap, w2, w3);
            }
        }

        CP_WAIT0();
        __syncthreads();
    }

    // normalize + write merged-head fp16 (proj A operand)
    const float inv0 = 1.0f / lrun0;
    const float inv1 = 1.0f / lrun1;
    const size_t r0 = (size_t)bb * SEQ + q0 + wm0 + g;
    const int colb = h * HDIM + t2;
    #pragma unroll
    for (int nt = 0; nt < 8; nt++) {
        *(uint32_t*)&g_ao_h[r0 * DMODEL + colb + nt * 8] =
            pack_h2(o[nt][0] * inv0, o[nt][1] * inv0);
        *(uint32_t*)&g_ao_h[(r0 + 8) * DMODEL + colb + nt * 8] =
            pack_h2(o[nt][2] * inv1, o[nt][3] * inv1);
    }
}

// ---------------------------------------------------------------------------
extern "C" void kernel_launch(void* const* d_in, const int* in_sizes, int n_in,
                              void* d_out, int out_size)
{
    const float* x      = (const float*)d_in[0];
    const float* w_attn = (const float*)d_in[1];
    const float* b_attn = (const float*)d_in[2];
    const float* w_proj = (const float*)d_in[3];
    const float* b_proj = (const float*)d_in[4];
    float* out = (float*)d_out;

    cudaFuncSetAttribute(attn_mma,
                         cudaFuncAttributeMaxDynamicSharedMemorySize, ATT_SMEM);
    cudaFuncSetAttribute(gemm_qkv_mma,
                         cudaFuncAttributeMaxDynamicSharedMemorySize, GSMEM);
    cudaFuncSetAttribute(gemm_proj_mma,
                         cudaFuncAttributeMaxDynamicSharedMemorySize, GSMEM);

    split_x<<<MTOT * DMODEL / 1024, 256>>>(x);
    trans_wa<<<dim3(3 * DMODEL / 32, DMODEL / 32), dim3(32, 8)>>>(w_attn);
    trans_wp<<<dim3(DMODEL / 32, DMODEL / 32), dim3(32, 8)>>>(w_proj);

    gemm_qkv_mma<<<dim3(3 * DMODEL / 128, MTOT / 128), 256, GSMEM>>>(b_attn);
    attn_mma<<<dim3(SEQ / 128, BATCH * NHEAD), 256, ATT_SMEM>>>();
    gemm_proj_mma<<<dim3(DMODEL / 128, MTOT / 128), 256, GSMEM>>>(b_proj, out);
}

// round 13
// speedup vs baseline: 2.2125x; 1.6014x over previous
#include <cuda_runtime.h>
#include <cuda_fp16.h>
#include <cstdint>

// ---------------------------------------------------------------------------
// GPT-2 attention block, all-tensor-core, single-pass fp16 mma.sync.
// fp32->fp16 rounding residuals dropped on BOTH operands (~5e-4 normwise,
// threshold 1e-3).  fp32 accumulate everywhere.
//   split  : x -> fp16                       (once)
//   qkv    = x @ w_attn + b_attn             (emits q (x1/8), k, v fp16)
//   att    = causal flash attention          (emits att fp16)
//   out    = att @ w_proj + b_proj           (fp32 out)
// GEMM: CTA 128x128, warp 32x64, K-step 32, 2-stage, 2 CTAs/SM.
// ---------------------------------------------------------------------------

#define BATCH  4
#define SEQ    2048
#define DMODEL 1024
#define NHEAD  16
#define HDIM   64
#define MTOT   (BATCH * SEQ)
#define GK     1024

__device__ __half g_x_h[(size_t)MTOT * DMODEL];
__device__ __half g_ao_h[(size_t)MTOT * DMODEL];
__device__ __half g_wa_h[3 * DMODEL * DMODEL];
__device__ __half g_wp_h[DMODEL * DMODEL];
#define QKV_ELEMS ((size_t)NHEAD * BATCH * SEQ * HDIM)
__device__ __half g_q_h[QKV_ELEMS];
__device__ __half g_k_h[QKV_ELEMS];
__device__ __half g_v_h[QKV_ELEMS];

// ---------------------------------------------------------------------------
__device__ __forceinline__ uint32_t smem_to_u32(const void* p) {
    uint32_t a;
    asm("{ .reg .u64 t; cvta.to.shared.u64 t, %1; cvt.u32.u64 %0, t; }"
        : "=r"(a) : "l"(p));
    return a;
}
__device__ __forceinline__ void ldsm_x4(uint32_t& r0, uint32_t& r1,
                                        uint32_t& r2, uint32_t& r3, uint32_t a) {
    asm volatile("ldmatrix.sync.aligned.m8n8.x4.shared.b16 {%0,%1,%2,%3}, [%4];"
                 : "=r"(r0), "=r"(r1), "=r"(r2), "=r"(r3) : "r"(a));
}
__device__ __forceinline__ void ldsm_x4_t(uint32_t& r0, uint32_t& r1,
                                          uint32_t& r2, uint32_t& r3, uint32_t a) {
    asm volatile("ldmatrix.sync.aligned.m8n8.x4.trans.shared.b16 {%0,%1,%2,%3}, [%4];"
                 : "=r"(r0), "=r"(r1), "=r"(r2), "=r"(r3) : "r"(a));
}
__device__ __forceinline__ void mma16816(float* d, const uint32_t* a,
                                         uint32_t b0, uint32_t b1) {
    asm volatile(
        "mma.sync.aligned.m16n8k16.row.col.f32.f16.f16.f32 "
        "{%0,%1,%2,%3}, {%4,%5,%6,%7}, {%8,%9}, {%0,%1,%2,%3};"
        : "+f"(d[0]), "+f"(d[1]), "+f"(d[2]), "+f"(d[3])
        : "r"(a[0]), "r"(a[1]), "r"(a[2]), "r"(a[3]), "r"(b0), "r"(b1));
}
#define CP_ASYNC16(dst, src) \
    asm volatile("cp.async.cg.shared.global [%0], [%1], 16;" :: "r"(dst), "l"(src) : "memory")
#define CP_COMMIT() asm volatile("cp.async.commit_group;" ::: "memory")
#define CP_WAIT0()  asm volatile("cp.async.wait_group 0;" ::: "memory")

__device__ __forceinline__ uint32_t pack_h2(float x, float y) {
    __half2 h = __floats2half2_rn(x, y);
    return *(uint32_t*)&h;
}

// ---------------------------------------------------------------------------
__global__ __launch_bounds__(256)
void split_x(const float* __restrict__ x)
{
    const size_t i = ((size_t)blockIdx.x * 256 + threadIdx.x) * 4;
    float4 v = *(const float4*)(x + i);
    *(uint2*)&g_x_h[i] = make_uint2(pack_h2(v.x, v.y), pack_h2(v.z, v.w));
}

__device__ __forceinline__ void transpose_body(
    const float* __restrict__ w, __half* __restrict__ o, int K, int N)
{
    __shared__ float t[32][33];
    const int n0 = blockIdx.x * 32, k0 = blockIdx.y * 32;
    const int tx = threadIdx.x, ty = threadIdx.y;
    #pragma unroll
    for (int i = ty; i < 32; i += 8)
        t[i][tx] = w[(size_t)(k0 + i) * N + n0 + tx];
    __syncthreads();
    #pragma unroll
    for (int i = ty; i < 32; i += 8)
        o[(size_t)(n0 + i) * K + k0 + tx] = __float2half(t[tx][i]);
}
__global__ void trans_wa(const float* __restrict__ w) {
    transpose_body(w, g_wa_h, DMODEL, 3 * DMODEL);
}
__global__ void trans_wp(const float* __restrict__ w) {
    transpose_body(w, g_wp_h, DMODEL, DMODEL);
}

// ---------------------------------------------------------------------------
// mma.sync GEMM: C = A(fp16) @ BT(fp16) + bias, single pass.
// CTA 128x128, K-step 32, 8 warps (4 M x 2 N), warp tile 32x64.
// 2-stage double buffer, 2 CTAs/SM, 1 sync/iter.
// ---------------------------------------------------------------------------
#define TK      32
#define NSTEP   (GK / TK)
#define ROWB    80
#define TILEB   (128 * ROWB)      // 10240
#define STAGEB  (2 * TILEB)       // 20480: A, B
#define GSMEM   (2 * STAGEB)      // 40960 -> 2 CTAs/SM

template <int MODE>
__device__ __forceinline__ void gemm_mma_body(
    const __half* __restrict__ A, const __half* __restrict__ BT,
    const float* __restrict__ bias, float* __restrict__ C, int N)
{
    extern __shared__ char smem[];
    const uint32_t sb = smem_to_u32(smem);
    const int tid  = threadIdx.x;
    const int lane = tid & 31;
    const int wid  = tid >> 5;
    const int wm   = wid & 3;
    const int wn   = wid >> 2;
    const int gid  = lane >> 2;
    const int tig  = lane & 3;
    const int m0   = blockIdx.y * 128;
    const int n0   = blockIdx.x * 128;

    float d[2][8][4];
    #pragma unroll
    for (int mt = 0; mt < 2; mt++)
        #pragma unroll
        for (int nt = 0; nt < 8; nt++)
            #pragma unroll
            for (int c = 0; c < 4; c++) d[mt][nt][c] = 0.0f;

    const uint32_t a_off = (uint32_t)((wm * 32 + (lane & 7) + ((lane >> 3) & 1) * 8) * ROWB
                                      + (lane >> 4) * 16);
    const uint32_t b_off = (uint32_t)((wn * 64 + ((lane >> 4) & 1) * 8 + (lane & 7)) * ROWB
                                      + ((lane >> 3) & 1) * 16);

    const int lrow = tid >> 1;
    const int lc   = (tid & 1) * 2;
    auto load_stage = [&](int t, int s) {
        const int k0 = t * TK;
        const uint32_t sbase = sb + s * STAGEB;
        const size_t ga = (size_t)(m0 + lrow) * GK + k0 + lc * 8;
        const size_t gb = (size_t)(n0 + lrow) * GK + k0 + lc * 8;
        const uint32_t so = (uint32_t)(lrow * ROWB + lc * 16);
        CP_ASYNC16(sbase + so,              A  + ga);
        CP_ASYNC16(sbase + so + 16,         A  + ga + 8);
        CP_ASYNC16(sbase + TILEB + so,      BT + gb);
        CP_ASYNC16(sbase + TILEB + so + 16, BT + gb + 8);
        CP_COMMIT();
    };

    load_stage(0, 0);

    #pragma unroll 1
    for (int t = 0; t < NSTEP; t++) {
        const int b = t & 1;
        CP_WAIT0();
        __syncthreads();
        if (t + 1 < NSTEP) load_stage(t + 1, b ^ 1);

        const uint32_t ah_base = sb + b * STAGEB + a_off;
        const uint32_t bh_base = sb + b * STAGEB + TILEB + b_off;

        #pragma unroll
        for (int kk = 0; kk < 2; kk++) {
            const uint32_t ko = kk * 32;
            uint32_t Af[2][4];
            ldsm_x4(Af[0][0], Af[0][1], Af[0][2], Af[0][3], ah_base + ko);
            ldsm_x4(Af[1][0], Af[1][1], Af[1][2], Af[1][3], ah_base + 16 * ROWB + ko);

            uint32_t Bh[8][2];
            #pragma unroll
            for (int p = 0; p < 4; p++)
                ldsm_x4(Bh[2 * p][0], Bh[2 * p][1], Bh[2 * p + 1][0], Bh[2 * p + 1][1],
                        bh_base + p * 16 * ROWB + ko);

            #pragma unroll
            for (int mt = 0; mt < 2; mt++)
                #pragma unroll
                for (int nt = 0; nt < 8; nt++)
                    mma16816(d[mt][nt], Af[mt], Bh[nt][0], Bh[nt][1]);
        }
    }

    if (MODE == 0) {
        #pragma unroll
        for (int nt = 0; nt < 8; nt++) {
            const int col = n0 + wn * 64 + nt * 8 + tig * 2;
            const float bx = __ldg(&bias[col]);
            const float by = __ldg(&bias[col + 1]);
            #pragma unroll
            for (int mt = 0; mt < 2; mt++) {
                const size_t r0 = (size_t)(m0 + wm * 32 + mt * 16 + gid);
                *(float2*)&C[r0 * N + col] =
                    make_float2(d[mt][nt][0] + bx, d[mt][nt][1] + by);
                *(float2*)&C[(r0 + 8) * N + col] =
                    make_float2(d[mt][nt][2] + bx, d[mt][nt][3] + by);
            }
        }
    } else {
        // qkv epilogue: q -> fp16 scaled 1/8, k/v -> fp16, head-separated
        #pragma unroll
        for (int nt = 0; nt < 8; nt++) {
            const int col = n0 + wn * 64 + nt * 8 + tig * 2;
            const float bx = __ldg(&bias[col]);
            const float by = __ldg(&bias[col + 1]);
            const int sel = col >> 10;
            const float scl = (sel == 0) ? 0.125f : 1.0f;
            __half* dh = (sel == 0) ? g_q_h : (sel == 1) ? g_k_h : g_v_h;
            const int hh = (col >> 6) & 15;
            const int dd = col & 63;
            #pragma unroll
            for (int mt = 0; mt < 2; mt++) {
                const int row = m0 + wm * 32 + mt * 16 + gid;
                const int bb = row >> 11, ss = row & 2047;
                const size_t base = ((size_t)(bb * NHEAD + hh) * SEQ + ss) * HDIM + dd;
                *(uint32_t*)&dh[base] =
                    pack_h2((d[mt][nt][0] + bx) * scl, (d[mt][nt][1] + by) * scl);
                *(uint32_t*)&dh[base + 8 * HDIM] =
                    pack_h2((d[mt][nt][2] + bx) * scl, (d[mt][nt][3] + by) * scl);
            }
        }
    }
}

__global__ __launch_bounds__(256, 2)
void gemm_qkv_mma(const float* __restrict__ bias)
{
    gemm_mma_body<1>(g_x_h, g_wa_h, bias, nullptr, 3 * DMODEL);
}
__global__ __launch_bounds__(256, 2)
void gemm_proj_mma(const float* __restrict__ bias, float* __restrict__ out)
{
    gemm_mma_body<0>(g_ao_h, g_wp_h, bias, out, DMODEL);
}

// ---------------------------------------------------------------------------
// Causal flash attention, single-pass fp16.
// CTA = (128 q rows, bh), 8 warps x m16, KV tile 64, double buffered.
// ---------------------------------------------------------------------------
#define ASTR   144
#define SQ_H   0
#define AKV0   (128 * ASTR)                    // 18432
#define KVBUF  (2 * 64 * ASTR)                 // 18432 (K, V)
#define SKV(s, t) (AKV0 + (s) * KVBUF + (t) * (64 * ASTR))
#define ATT_SMEM (AKV0 + 2 * KVBUF)            // 55296

__global__ __launch_bounds__(256, 2)
void attn_mma()
{
    extern __shared__ char smem[];
    const uint32_t sb = smem_to_u32(smem);
    const int tid  = threadIdx.x;
    const int wid  = tid >> 5;
    const int lane = tid & 31;
    const int g    = lane >> 2;
    const int t2   = (lane & 3) * 2;
    const int qi   = (int)(gridDim.x - 1 - blockIdx.x);  // heavy tiles first
    const int bh   = blockIdx.y;
    const int bb   = bh >> 4;
    const int h    = bh & 15;
    const int q0   = qi * 128;
    const int wm0  = wid * 16;

    const size_t head_base = (size_t)bh * SEQ * HDIM;

    auto load_kv = [&](int jt, int s) {
        #pragma unroll
        for (int tp = 0; tp < 2; tp++) {
            const __half* bp = (tp == 0) ? g_k_h : g_v_h;
            #pragma unroll
            for (int j = 0; j < 2; j++) {
                int idx = tid + (tp * 2 + j) * 256;
                int row = (idx >> 3) & 63;
                int c   = idx & 7;
                uint32_t dst = sb + SKV(s, tp) + row * ASTR + c * 16;
                const __half* src =
                    bp + head_base + (size_t)(jt * 64 + row) * HDIM + c * 8;
                CP_ASYNC16(dst, src);
            }
        }
        CP_COMMIT();
    };

    load_kv(0, 0);

    {
        const __half* q_g = g_q_h + head_base + (size_t)q0 * HDIM;
        #pragma unroll
        for (int i = 0; i < 4; i++) {
            int idx = tid + i * 256;
            int row = idx >> 3;
            int c   = idx & 7;
            *(uint4*)(smem + SQ_H + row * ASTR + c * 16) =
                *(const uint4*)(q_g + (size_t)row * HDIM + c * 8);
        }
    }
    CP_WAIT0();
    __syncthreads();

    const uint32_t qaddr = sb + SQ_H +
        (uint32_t)((wm0 + (lane & 7) + ((lane >> 3) & 1) * 8) * ASTR + (lane >> 4) * 16);

    float o[8][4];
    #pragma unroll
    for (int nt = 0; nt < 8; nt++)
        #pragma unroll
        for (int c = 0; c < 4; c++) o[nt][c] = 0.0f;
    float mrun0 = -1e30f, mrun1 = -1e30f, lrun0 = 0.0f, lrun1 = 0.0f;

    const int njt = 2 * qi + 2;
    const uint32_t k_off =
        (uint32_t)(((lane & 7) + ((lane >> 4) & 1) * 8) * ASTR + ((lane >> 3) & 1) * 16);
    const uint32_t v_off =
        (uint32_t)(((lane & 7) + ((lane >> 3) & 1) * 8) * ASTR + (lane >> 4) * 16);

    #pragma unroll 1
    for (int jt = 0; jt < njt; jt++) {
        const int bfr = jt & 1;
        if (jt + 1 < njt) load_kv(jt + 1, bfr ^ 1);

        float s[8][4];
        #pragma unroll
        for (int nt = 0; nt < 8; nt++)
            #pragma unroll
            for (int c = 0; c < 4; c++) s[nt][c] = 0.0f;

        const uint32_t kaddr = sb + SKV(bfr, 0) + k_off;
        #pragma unroll
        for (int kt = 0; kt < 4; kt++) {
            uint32_t qf[4];
            ldsm_x4(qf[0], qf[1], qf[2], qf[3], qaddr + kt * 32);
            #pragma unroll
            for (int np = 0; np < 4; np++) {
                uint32_t a0, a1, a2, a3;
                ldsm_x4(a0, a1, a2, a3, kaddr + np * (16 * ASTR) + kt * 32);
                mma16816(s[2 * np],     qf, a0, a1);
                mma16816(s[2 * np + 1], qf, a2, a3);
            }
        }

        if (jt * 64 + 63 > q0 + wm0) {
            const int row0 = q0 + wm0 + g;
            #pragma unroll
            for (int nt = 0; nt < 8; nt++) {
                const int col = jt * 64 + nt * 8 + t2;
                #pragma unroll
                for (int c = 0; c < 4; c++) {
                    int cc = col + (c & 1);
                    int rr = row0 + (c >> 1) * 8;
                    if (cc > rr) s[nt][c] = -1e30f;
                }
            }
        }

        float mt0 = -1e30f, mt1 = -1e30f;
        #pragma unroll
        for (int nt = 0; nt < 8; nt++) {
            mt0 = fmaxf(mt0, fmaxf(s[nt][0], s[nt][1]));
            mt1 = fmaxf(mt1, fmaxf(s[nt][2], s[nt][3]));
        }
        mt0 = fmaxf(mt0, __shfl_xor_sync(0xffffffffu, mt0, 1));
        mt0 = fmaxf(mt0, __shfl_xor_sync(0xffffffffu, mt0, 2));
        mt1 = fmaxf(mt1, __shfl_xor_sync(0xffffffffu, mt1, 1));
        mt1 = fmaxf(mt1, __shfl_xor_sync(0xffffffffu, mt1, 2));

        const float mn0 = fmaxf(mrun0, mt0);
        const float mn1 = fmaxf(mrun1, mt1);
        const float f0 = __expf(mrun0 - mn0);
        const float f1 = __expf(mrun1 - mn1);
        mrun0 = mn0; mrun1 = mn1;

        float lt0 = 0.0f, lt1 = 0.0f;
        #pragma unroll
        for (int nt = 0; nt < 8; nt++) {
            s[nt][0] = __expf(s[nt][0] - mn0); lt0 += s[nt][0];
            s[nt][1] = __expf(s[nt][1] - mn0); lt0 += s[nt][1];
            s[nt][2] = __expf(s[nt][2] - mn1); lt1 += s[nt][2];
            s[nt][3] = __expf(s[nt][3] - mn1); lt1 += s[nt][3];
        }
        lt0 += __shfl_xor_sync(0xffffffffu, lt0, 1);
        lt0 += __shfl_xor_sync(0xffffffffu, lt0, 2);
        lt1 += __shfl_xor_sync(0xffffffffu, lt1, 1);
        lt1 += __shfl_xor_sync(0xffffffffu, lt1, 2);
        lrun0 = lrun0 * f0 + lt0;
        lrun1 = lrun1 * f1 + lt1;
        #pragma unroll
        for (int nt = 0; nt < 8; nt++) {
            o[nt][0] *= f0; o[nt][1] *= f0;
            o[nt][2] *= f1; o[nt][3] *= f1;
        }

        // O += P @ V, single pass
        const uint32_t vaddr = sb + SKV(bfr, 1) + v_off;
        #pragma unroll
        for (int kt = 0; kt < 4; kt++) {
            uint32_t ap[4];
            ap[0] = pack_h2(s[2 * kt][0],     s[2 * kt][1]);
            ap[1] = pack_h2(s[2 * kt][2],     s[2 * kt][3]);
            ap[2] = pack_h2(s[2 * kt + 1][0], s[2 * kt + 1][1]);
            ap[3] = pack_h2(s[2 * kt + 1][2], s[2 * kt + 1][3]);
            #pragma unroll
            for (int np = 0; np < 4; np++) {
                uint32_t v0, v1, v2, v3;
                ldsm_x4_t(v0, v1, v2, v3, vaddr + kt * (16 * ASTR) + np * 32);
                mma16816(o[2 * np],     ap, v0, v1);
                mma16816(o[2 * np + 1], ap, v2, v3);
            }
        }

        CP_WAIT0();
        __syncthreads();
    }

    // normalize + write merged-head fp16 (proj A operand)
    const float inv0 = 1.0f / lrun0;
    const float inv1 = 1.0f / lrun1;
    const size_t r0 = (size_t)bb * SEQ + q0 + wm0 + g;
    const int colb = h * HDIM + t2;
    #pragma unroll
    for (int nt = 0; nt < 8; nt++) {
        *(uint32_t*)&g_ao_h[r0 * DMODEL + colb + nt * 8] =
            pack_h2(o[nt][0] * inv0, o[nt][1] * inv0);
        *(uint32_t*)&g_ao_h[(r0 + 8) * DMODEL + colb + nt * 8] =
            pack_h2(o[nt][2] * inv1, o[nt][3] * inv1);
    }
}

// ---------------------------------------------------------------------------
extern "C" void kernel_launch(void* const* d_in, const int* in_sizes, int n_in,
                              void* d_out, int out_size)
{
    const float* x      = (const float*)d_in[0];
    const float* w_attn = (const float*)d_in[1];
    const float* b_attn = (const float*)d_in[2];
    const float* w_proj = (const float*)d_in[3];
    const float* b_proj = (const float*)d_in[4];
    float* out = (float*)d_out;

    cudaFuncSetAttribute(attn_mma,
                         cudaFuncAttributeMaxDynamicSharedMemorySize, ATT_SMEM);
    cudaFuncSetAttribute(gemm_qkv_mma,
                         cudaFuncAttributeMaxDynamicSharedMemorySize, GSMEM);
    cudaFuncSetAttribute(gemm_proj_mma,
                         cudaFuncAttributeMaxDynamicSharedMemorySize, GSMEM);

    split_x<<<MTOT * DMODEL / 1024, 256>>>(x);
    trans_wa<<<dim3(3 * DMODEL / 32, DMODEL / 32), dim3(32, 8)>>>(w_attn);
    trans_wp<<<dim3(DMODEL / 32, DMODEL / 32), dim3(32, 8)>>>(w_proj);

    gemm_qkv_mma<<<dim3(3 * DMODEL / 128, MTOT / 128), 256, GSMEM>>>(b_attn);
    attn_mma<<<dim3(SEQ / 128, BATCH * NHEAD), 256, ATT_SMEM>>>();
    gemm_proj_mma<<<dim3(DMODEL / 128, MTOT / 128), 256, GSMEM>>>(b_proj, out);
}

// round 14
// speedup vs baseline: 2.6307x; 1.1890x over previous
#include <cuda_runtime.h>
#include <cuda_fp16.h>
#include <cstdint>

// ---------------------------------------------------------------------------
// GPT-2 attention block, all-tensor-core, single-pass fp16 mma.sync.
// fp32 accumulate everywhere; fp16 rounding residual ~5e-4 (threshold 1e-3).
//   split  : x -> fp16                       (once)
//   qkv    = x @ w_attn + b_attn             (emits q (x1/8), k, v fp16)
//   att    = causal flash attention          (emits att fp16)
//   out    = att @ w_proj + b_proj           (fp32 out)
// GEMM: CTA 128x128, warp 32x64, K-step 64 (16 iters), 2-stage, 2 CTAs/SM.
// ---------------------------------------------------------------------------

#define BATCH  4
#define SEQ    2048
#define DMODEL 1024
#define NHEAD  16
#define HDIM   64
#define MTOT   (BATCH * SEQ)
#define GK     1024

__device__ __half g_x_h[(size_t)MTOT * DMODEL];
__device__ __half g_ao_h[(size_t)MTOT * DMODEL];
__device__ __half g_wa_h[3 * DMODEL * DMODEL];
__device__ __half g_wp_h[DMODEL * DMODEL];
#define QKV_ELEMS ((size_t)NHEAD * BATCH * SEQ * HDIM)
__device__ __half g_q_h[QKV_ELEMS];
__device__ __half g_k_h[QKV_ELEMS];
__device__ __half g_v_h[QKV_ELEMS];

// ---------------------------------------------------------------------------
__device__ __forceinline__ uint32_t smem_to_u32(const void* p) {
    uint32_t a;
    asm("{ .reg .u64 t; cvta.to.shared.u64 t, %1; cvt.u32.u64 %0, t; }"
        : "=r"(a) : "l"(p));
    return a;
}
__device__ __forceinline__ void ldsm_x4(uint32_t& r0, uint32_t& r1,
                                        uint32_t& r2, uint32_t& r3, uint32_t a) {
    asm volatile("ldmatrix.sync.aligned.m8n8.x4.shared.b16 {%0,%1,%2,%3}, [%4];"
                 : "=r"(r0), "=r"(r1), "=r"(r2), "=r"(r3) : "r"(a));
}
__device__ __forceinline__ void ldsm_x4_t(uint32_t& r0, uint32_t& r1,
                                          uint32_t& r2, uint32_t& r3, uint32_t a) {
    asm volatile("ldmatrix.sync.aligned.m8n8.x4.trans.shared.b16 {%0,%1,%2,%3}, [%4];"
                 : "=r"(r0), "=r"(r1), "=r"(r2), "=r"(r3) : "r"(a));
}
__device__ __forceinline__ void mma16816(float* d, const uint32_t* a,
                                         uint32_t b0, uint32_t b1) {
    asm volatile(
        "mma.sync.aligned.m16n8k16.row.col.f32.f16.f16.f32 "
        "{%0,%1,%2,%3}, {%4,%5,%6,%7}, {%8,%9}, {%0,%1,%2,%3};"
        : "+f"(d[0]), "+f"(d[1]), "+f"(d[2]), "+f"(d[3])
        : "r"(a[0]), "r"(a[1]), "r"(a[2]), "r"(a[3]), "r"(b0), "r"(b1));
}
#define CP_ASYNC16(dst, src) \
    asm volatile("cp.async.cg.shared.global [%0], [%1], 16;" :: "r"(dst), "l"(src) : "memory")
#define CP_COMMIT() asm volatile("cp.async.commit_group;" ::: "memory")
#define CP_WAIT0()  asm volatile("cp.async.wait_group 0;" ::: "memory")

__device__ __forceinline__ uint32_t pack_h2(float x, float y) {
    __half2 h = __floats2half2_rn(x, y);
    return *(uint32_t*)&h;
}

// ---------------------------------------------------------------------------
__global__ __launch_bounds__(256)
void split_x(const float* __restrict__ x)
{
    const size_t i = ((size_t)blockIdx.x * 256 + threadIdx.x) * 4;
    float4 v = *(const float4*)(x + i);
    *(uint2*)&g_x_h[i] = make_uint2(pack_h2(v.x, v.y), pack_h2(v.z, v.w));
}

__device__ __forceinline__ void transpose_body(
    const float* __restrict__ w, __half* __restrict__ o, int K, int N)
{
    __shared__ float t[32][33];
    const int n0 = blockIdx.x * 32, k0 = blockIdx.y * 32;
    const int tx = threadIdx.x, ty = threadIdx.y;
    #pragma unroll
    for (int i = ty; i < 32; i += 8)
        t[i][tx] = w[(size_t)(k0 + i) * N + n0 + tx];
    __syncthreads();
    #pragma unroll
    for (int i = ty; i < 32; i += 8)
        o[(size_t)(n0 + i) * K + k0 + tx] = __float2half(t[tx][i]);
}
__global__ void trans_wa(const float* __restrict__ w) {
    transpose_body(w, g_wa_h, DMODEL, 3 * DMODEL);
}
__global__ void trans_wp(const float* __restrict__ w) {
    transpose_body(w, g_wp_h, DMODEL, DMODEL);
}

// ---------------------------------------------------------------------------
// mma.sync GEMM: C = A(fp16) @ BT(fp16) + bias, single pass.
// CTA 128x128, K-step 64 (16 iters), 8 warps (4 M x 2 N), warp tile 32x64.
// ROWB=144: 128B data + 16B pad -> 16-aligned, conflict-free ldsm phases.
// ---------------------------------------------------------------------------
#define TK      64
#define NSTEP   (GK / TK)         // 16
#define ROWB    144
#define TILEB   (128 * ROWB)      // 18432
#define STAGEB  (2 * TILEB)       // 36864: A, B
#define GSMEM   (2 * STAGEB)      // 73728 -> 2 CTAs/SM

template <int MODE>
__device__ __forceinline__ void gemm_mma_body(
    const __half* __restrict__ A, const __half* __restrict__ BT,
    const float* __restrict__ bias, float* __restrict__ C, int N)
{
    extern __shared__ char smem[];
    const uint32_t sb = smem_to_u32(smem);
    const int tid  = threadIdx.x;
    const int lane = tid & 31;
    const int wid  = tid >> 5;
    const int wm   = wid & 3;
    const int wn   = wid >> 2;
    const int gid  = lane >> 2;
    const int tig  = lane & 3;
    const int m0   = blockIdx.y * 128;
    const int n0   = blockIdx.x * 128;

    float d[2][8][4];
    #pragma unroll
    for (int mt = 0; mt < 2; mt++)
        #pragma unroll
        for (int nt = 0; nt < 8; nt++)
            #pragma unroll
            for (int c = 0; c < 4; c++) d[mt][nt][c] = 0.0f;

    const uint32_t a_off = (uint32_t)((wm * 32 + (lane & 7) + ((lane >> 3) & 1) * 8) * ROWB
                                      + (lane >> 4) * 16);
    const uint32_t b_off = (uint32_t)((wn * 64 + ((lane >> 4) & 1) * 8 + (lane & 7)) * ROWB
                                      + ((lane >> 3) & 1) * 16);

    // loader: 4 A-chunks + 4 B-chunks (16B) per thread per stage
    auto load_stage = [&](int t, int s) {
        const int k0 = t * TK;
        const uint32_t sbase = sb + s * STAGEB;
        #pragma unroll
        for (int i = 0; i < 4; i++) {
            int idx = tid + i * 256;          // 0..1023
            int row = idx >> 3;               // 0..127
            int c   = idx & 7;                // 16B chunk in 128B row
            const uint32_t so = (uint32_t)(row * ROWB + c * 16);
            CP_ASYNC16(sbase + so,         A  + (size_t)(m0 + row) * GK + k0 + c * 8);
            CP_ASYNC16(sbase + TILEB + so, BT + (size_t)(n0 + row) * GK + k0 + c * 8);
        }
        CP_COMMIT();
    };

    load_stage(0, 0);

    #pragma unroll 1
    for (int t = 0; t < NSTEP; t++) {
        const int b = t & 1;
        CP_WAIT0();
        __syncthreads();
        if (t + 1 < NSTEP) load_stage(t + 1, b ^ 1);

        const uint32_t ah_base = sb + b * STAGEB + a_off;
        const uint32_t bh_base = sb + b * STAGEB + TILEB + b_off;

        #pragma unroll
        for (int kk = 0; kk < 4; kk++) {
            const uint32_t ko = kk * 32;
            uint32_t Af[2][4];
            ldsm_x4(Af[0][0], Af[0][1], Af[0][2], Af[0][3], ah_base + ko);
            ldsm_x4(Af[1][0], Af[1][1], Af[1][2], Af[1][3], ah_base + 16 * ROWB + ko);

            uint32_t Bh[8][2];
            #pragma unroll
            for (int p = 0; p < 4; p++)
                ldsm_x4(Bh[2 * p][0], Bh[2 * p][1], Bh[2 * p + 1][0], Bh[2 * p + 1][1],
                        bh_base + p * 16 * ROWB + ko);

            #pragma unroll
            for (int mt = 0; mt < 2; mt++)
                #pragma unroll
                for (int nt = 0; nt < 8; nt++)
                    mma16816(d[mt][nt], Af[mt], Bh[nt][0], Bh[nt][1]);
        }
    }

    if (MODE == 0) {
        #pragma unroll
        for (int nt = 0; nt < 8; nt++) {
            const int col = n0 + wn * 64 + nt * 8 + tig * 2;
            const float bx = __ldg(&bias[col]);
            const float by = __ldg(&bias[col + 1]);
            #pragma unroll
            for (int mt = 0; mt < 2; mt++) {
                const size_t r0 = (size_t)(m0 + wm * 32 + mt * 16 + gid);
                *(float2*)&C[r0 * N + col] =
                    make_float2(d[mt][nt][0] + bx, d[mt][nt][1] + by);
                *(float2*)&C[(r0 + 8) * N + col] =
                    make_float2(d[mt][nt][2] + bx, d[mt][nt][3] + by);
            }
        }
    } else {
        // qkv epilogue: q -> fp16 scaled 1/8, k/v -> fp16, head-separated
        #pragma unroll
        for (int nt = 0; nt < 8; nt++) {
            const int col = n0 + wn * 64 + nt * 8 + tig * 2;
            const float bx = __ldg(&bias[col]);
            const float by = __ldg(&bias[col + 1]);
            const int sel = col >> 10;
            const float scl = (sel == 0) ? 0.125f : 1.0f;
            __half* dh = (sel == 0) ? g_q_h : (sel == 1) ? g_k_h : g_v_h;
            const int hh = (col >> 6) & 15;
            const int dd = col & 63;
            #pragma unroll
            for (int mt = 0; mt < 2; mt++) {
                const int row = m0 + wm * 32 + mt * 16 + gid;
                const int bb = row >> 11, ss = row & 2047;
                const size_t base = ((size_t)(bb * NHEAD + hh) * SEQ + ss) * HDIM + dd;
                *(uint32_t*)&dh[base] =
                    pack_h2((d[mt][nt][0] + bx) * scl, (d[mt][nt][1] + by) * scl);
                *(uint32_t*)&dh[base + 8 * HDIM] =
                    pack_h2((d[mt][nt][2] + bx) * scl, (d[mt][nt][3] + by) * scl);
            }
        }
    }
}

__global__ __launch_bounds__(256, 2)
void gemm_qkv_mma(const float* __restrict__ bias)
{
    gemm_mma_body<1>(g_x_h, g_wa_h, bias, nullptr, 3 * DMODEL);
}
__global__ __launch_bounds__(256, 2)
void gemm_proj_mma(const float* __restrict__ bias, float* __restrict__ out)
{
    gemm_mma_body<0>(g_ao_h, g_wp_h, bias, out, DMODEL);
}

// ---------------------------------------------------------------------------
// Causal flash attention, single-pass fp16 (unchanged from round 13).
// CTA = (128 q rows, bh), 8 warps x m16, KV tile 64, double buffered.
// ---------------------------------------------------------------------------
#define ASTR   144
#define SQ_H   0
#define AKV0   (128 * ASTR)                    // 18432
#define KVBUF  (2 * 64 * ASTR)                 // 18432 (K, V)
#define SKV(s, t) (AKV0 + (s) * KVBUF + (t) * (64 * ASTR))
#define ATT_SMEM (AKV0 + 2 * KVBUF)            // 55296

__global__ __launch_bounds__(256, 2)
void attn_mma()
{
    extern __shared__ char smem[];
    const uint32_t sb = smem_to_u32(smem);
    const int tid  = threadIdx.x;
    const int wid  = tid >> 5;
    const int lane = tid & 31;
    const int g    = lane >> 2;
    const int t2   = (lane & 3) * 2;
    const int qi   = (int)(gridDim.x - 1 - blockIdx.x);  // heavy tiles first
    const int bh   = blockIdx.y;
    const int bb   = bh >> 4;
    const int h    = bh & 15;
    const int q0   = qi * 128;
    const int wm0  = wid * 16;

    const size_t head_base = (size_t)bh * SEQ * HDIM;

    auto load_kv = [&](int jt, int s) {
        #pragma unroll
        for (int tp = 0; tp < 2; tp++) {
            const __half* bp = (tp == 0) ? g_k_h : g_v_h;
            #pragma unroll
            for (int j = 0; j < 2; j++) {
                int idx = tid + (tp * 2 + j) * 256;
                int row = (idx >> 3) & 63;
                int c   = idx & 7;
                uint32_t dst = sb + SKV(s, tp) + row * ASTR + c * 16;
                const __half* src =
                    bp + head_base + (size_t)(jt * 64 + row) * HDIM + c * 8;
                CP_ASYNC16(dst, src);
            }
        }
        CP_COMMIT();
    };

    load_kv(0, 0);

    {
        const __half* q_g = g_q_h + head_base + (size_t)q0 * HDIM;
        #pragma unroll
        for (int i = 0; i < 4; i++) {
            int idx = tid + i * 256;
            int row = idx >> 3;
            int c   = idx & 7;
            *(uint4*)(smem + SQ_H + row * ASTR + c * 16) =
                *(const uint4*)(q_g + (size_t)row * HDIM + c * 8);
        }
    }
    CP_WAIT0();
    __syncthreads();

    const uint32_t qaddr = sb + SQ_H +
        (uint32_t)((wm0 + (lane & 7) + ((lane >> 3) & 1) * 8) * ASTR + (lane >> 4) * 16);

    float o[8][4];
    #pragma unroll
    for (int nt = 0; nt < 8; nt++)
        #pragma unroll
        for (int c = 0; c < 4; c++) o[nt][c] = 0.0f;
    float mrun0 = -1e30f, mrun1 = -1e30f, lrun0 = 0.0f, lrun1 = 0.0f;

    const int njt = 2 * qi + 2;
    const uint32_t k_off =
        (uint32_t)(((lane & 7) + ((lane >> 4) & 1) * 8) * ASTR + ((lane >> 3) & 1) * 16);
    const uint32_t v_off =
        (uint32_t)(((lane & 7) + ((lane >> 3) & 1) * 8) * ASTR + (lane >> 4) * 16);

    #pragma unroll 1
    for (int jt = 0; jt < njt; jt++) {
        const int bfr = jt & 1;
        if (jt + 1 < njt) load_kv(jt + 1, bfr ^ 1);

        float s[8][4];
        #pragma unroll
        for (int nt = 0; nt < 8; nt++)
            #pragma unroll
            for (int c = 0; c < 4; c++) s[nt][c] = 0.0f;

        const uint32_t kaddr = sb + SKV(bfr, 0) + k_off;
        #pragma unroll
        for (int kt = 0; kt < 4; kt++) {
            uint32_t qf[4];
            ldsm_x4(qf[0], qf[1], qf[2], qf[3], qaddr + kt * 32);
            #pragma unroll
            for (int np = 0; np < 4; np++) {
                uint32_t a0, a1, a2, a3;
                ldsm_x4(a0, a1, a2, a3, kaddr + np * (16 * ASTR) + kt * 32);
                mma16816(s[2 * np],     qf, a0, a1);
                mma16816(s[2 * np + 1], qf, a2, a3);
            }
        }

        if (jt * 64 + 63 > q0 + wm0) {
            const int row0 = q0 + wm0 + g;
            #pragma unroll
            for (int nt = 0; nt < 8; nt++) {
                const int col = jt * 64 + nt * 8 + t2;
                #pragma unroll
                for (int c = 0; c < 4; c++) {
                    int cc = col + (c & 1);
                    int rr = row0 + (c >> 1) * 8;
                    if (cc > rr) s[nt][c] = -1e30f;
                }
            }
        }

        float mt0 = -1e30f, mt1 = -1e30f;
        #pragma unroll
        for (int nt = 0; nt < 8; nt++) {
            mt0 = fmaxf(mt0, fmaxf(s[nt][0], s[nt][1]));
            mt1 = fmaxf(mt1, fmaxf(s[nt][2], s[nt][3]));
        }
        mt0 = fmaxf(mt0, __shfl_xor_sync(0xffffffffu, mt0, 1));
        mt0 = fmaxf(mt0, __shfl_xor_sync(0xffffffffu, mt0, 2));
        mt1 = fmaxf(mt1, __shfl_xor_sync(0xffffffffu, mt1, 1));
        mt1 = fmaxf(mt1, __shfl_xor_sync(0xffffffffu, mt1, 2));

        const float mn0 = fmaxf(mrun0, mt0);
        const float mn1 = fmaxf(mrun1, mt1);
        const float f0 = __expf(mrun0 - mn0);
        const float f1 = __expf(mrun1 - mn1);
        mrun0 = mn0; mrun1 = mn1;

        float lt0 = 0.0f, lt1 = 0.0f;
        #pragma unroll
        for (int nt = 0; nt < 8; nt++) {
            s[nt][0] = __expf(s[nt][0] - mn0); lt0 += s[nt][0];
            s[nt][1] = __expf(s[nt][1] - mn0); lt0 += s[nt][1];
            s[nt][2] = __expf(s[nt][2] - mn1); lt1 += s[nt][2];
            s[nt][3] = __expf(s[nt][3] - mn1); lt1 += s[nt][3];
        }
        lt0 += __shfl_xor_sync(0xffffffffu, lt0, 1);
        lt0 += __shfl_xor_sync(0xffffffffu, lt0, 2);
        lt1 += __shfl_xor_sync(0xffffffffu, lt1, 1);
        lt1 += __shfl_xor_sync(0xffffffffu, lt1, 2);
        lrun0 = lrun0 * f0 + lt0;
        lrun1 = lrun1 * f1 + lt1;
        #pragma unroll
        for (int nt = 0; nt < 8; nt++) {
            o[nt][0] *= f0; o[nt][1] *= f0;
            o[nt][2] *= f1; o[nt][3] *= f1;
        }

        const uint32_t vaddr = sb + SKV(bfr, 1) + v_off;
        #pragma unroll
        for (int kt = 0; kt < 4; kt++) {
            uint32_t ap[4];
            ap[0] = pack_h2(s[2 * kt][0],     s[2 * kt][1]);
            ap[1] = pack_h2(s[2 * kt][2],     s[2 * kt][3]);
            ap[2] = pack_h2(s[2 * kt + 1][0], s[2 * kt + 1][1]);
            ap[3] = pack_h2(s[2 * kt + 1][2], s[2 * kt + 1][3]);
            #pragma unroll
            for (int np = 0; np < 4; np++) {
                uint32_t v0, v1, v2, v3;
                ldsm_x4_t(v0, v1, v2, v3, vaddr + kt * (16 * ASTR) + np * 32);
                mma16816(o[2 * np],     ap, v0, v1);
                mma16816(o[2 * np + 1], ap, v2, v3);
            }
        }

        CP_WAIT0();
        __syncthreads();
    }

    const float inv0 = 1.0f / lrun0;
    const float inv1 = 1.0f / lrun1;
    const size_t r0 = (size_t)bb * SEQ + q0 + wm0 + g;
    const int colb = h * HDIM + t2;
    #pragma unroll
    for (int nt = 0; nt < 8; nt++) {
        *(uint32_t*)&g_ao_h[r0 * DMODEL + colb + nt * 8] =
            pack_h2(o[nt][0] * inv0, o[nt][1] * inv0);
        *(uint32_t*)&g_ao_h[(r0 + 8) * DMODEL + colb + nt * 8] =
            pack_h2(o[nt][2] * inv1, o[nt][3] * inv1);
    }
}

// ---------------------------------------------------------------------------
extern "C" void kernel_launch(void* const* d_in, const int* in_sizes, int n_in,
                              void* d_out, int out_size)
{
    const float* x      = (const float*)d_in[0];
    const float* w_attn = (const float*)d_in[1];
    const float* b_attn = (const float*)d_in[2];
    const float* w_proj = (const float*)d_in[3];
    const float* b_proj = (const float*)d_in[4];
    float* out = (float*)d_out;

    cudaFuncSetAttribute(attn_mma,
                         cudaFuncAttributeMaxDynamicSharedMemorySize, ATT_SMEM);
    cudaFuncSetAttribute(gemm_qkv_mma,
                         cudaFuncAttributeMaxDynamicSharedMemorySize, GSMEM);
    cudaFuncSetAttribute(gemm_proj_mma,
                         cudaFuncAttributeMaxDynamicSharedMemorySize, GSMEM);

    split_x<<<MTOT * DMODEL / 1024, 256>>>(x);
    trans_wa<<<dim3(3 * DMODEL / 32, DMODEL / 32), dim3(32, 8)>>>(w_attn);
    trans_wp<<<dim3(DMODEL / 32, DMODEL / 32), dim3(32, 8)>>>(w_proj);

    gemm_qkv_mma<<<dim3(3 * DMODEL / 128, MTOT / 128), 256, GSMEM>>>(b_attn);
    attn_mma<<<dim3(SEQ / 128, BATCH * NHEAD), 256, ATT_SMEM>>>();
    gemm_proj_mma<<<dim3(DMODEL / 128, MTOT / 128), 256, GSMEM>>>(b_proj, out);
}

// round 15
// speedup vs baseline: 2.6439x; 1.0050x over previous
#include <cuda_runtime.h>
#include <cuda_fp16.h>
#include <cstdint>

// ---------------------------------------------------------------------------
// GPT-2 attention block, all-tensor-core, single-pass fp16 mma.sync.
// fp32 accumulate everywhere; fp16 rounding residual ~5e-4 (threshold 1e-3).
//   split  : x -> fp16                       (once)
//   qkv    = x @ w_attn + b_attn             (emits q (x1/8), k, v fp16)
//   att    = causal flash attention          (emits att fp16)
//   out    = att @ w_proj + b_proj           (fp32 out)
// GEMM: CTA 128x128, warp 32x64, K-step 64 (16 iters), 2-stage, 2 CTAs/SM.
// Attention: KV staged 128 rows/barrier, computed in 64-col halves;
//            fully-masked halves skipped (warp-uniform).
// ---------------------------------------------------------------------------

#define BATCH  4
#define SEQ    2048
#define DMODEL 1024
#define NHEAD  16
#define HDIM   64
#define MTOT   (BATCH * SEQ)
#define GK     1024

__device__ __half g_x_h[(size_t)MTOT * DMODEL];
__device__ __half g_ao_h[(size_t)MTOT * DMODEL];
__device__ __half g_wa_h[3 * DMODEL * DMODEL];
__device__ __half g_wp_h[DMODEL * DMODEL];
#define QKV_ELEMS ((size_t)NHEAD * BATCH * SEQ * HDIM)
__device__ __half g_q_h[QKV_ELEMS];
__device__ __half g_k_h[QKV_ELEMS];
__device__ __half g_v_h[QKV_ELEMS];

// ---------------------------------------------------------------------------
__device__ __forceinline__ uint32_t smem_to_u32(const void* p) {
    uint32_t a;
    asm("{ .reg .u64 t; cvta.to.shared.u64 t, %1; cvt.u32.u64 %0, t; }"
        : "=r"(a) : "l"(p));
    return a;
}
__device__ __forceinline__ void ldsm_x4(uint32_t& r0, uint32_t& r1,
                                        uint32_t& r2, uint32_t& r3, uint32_t a) {
    asm volatile("ldmatrix.sync.aligned.m8n8.x4.shared.b16 {%0,%1,%2,%3}, [%4];"
                 : "=r"(r0), "=r"(r1), "=r"(r2), "=r"(r3) : "r"(a));
}
__device__ __forceinline__ void ldsm_x4_t(uint32_t& r0, uint32_t& r1,
                                          uint32_t& r2, uint32_t& r3, uint32_t a) {
    asm volatile("ldmatrix.sync.aligned.m8n8.x4.trans.shared.b16 {%0,%1,%2,%3}, [%4];"
                 : "=r"(r0), "=r"(r1), "=r"(r2), "=r"(r3) : "r"(a));
}
__device__ __forceinline__ void mma16816(float* d, const uint32_t* a,
                                         uint32_t b0, uint32_t b1) {
    asm volatile(
        "mma.sync.aligned.m16n8k16.row.col.f32.f16.f16.f32 "
        "{%0,%1,%2,%3}, {%4,%5,%6,%7}, {%8,%9}, {%0,%1,%2,%3};"
        : "+f"(d[0]), "+f"(d[1]), "+f"(d[2]), "+f"(d[3])
        : "r"(a[0]), "r"(a[1]), "r"(a[2]), "r"(a[3]), "r"(b0), "r"(b1));
}
#define CP_ASYNC16(dst, src) \
    asm volatile("cp.async.cg.shared.global [%0], [%1], 16;" :: "r"(dst), "l"(src) : "memory")
#define CP_COMMIT() asm volatile("cp.async.commit_group;" ::: "memory")
#define CP_WAIT0()  asm volatile("cp.async.wait_group 0;" ::: "memory")

__device__ __forceinline__ uint32_t pack_h2(float x, float y) {
    __half2 h = __floats2half2_rn(x, y);
    return *(uint32_t*)&h;
}

// ---------------------------------------------------------------------------
__global__ __launch_bounds__(256)
void split_x(const float* __restrict__ x)
{
    const size_t i = ((size_t)blockIdx.x * 256 + threadIdx.x) * 4;
    float4 v = *(const float4*)(x + i);
    *(uint2*)&g_x_h[i] = make_uint2(pack_h2(v.x, v.y), pack_h2(v.z, v.w));
}

__device__ __forceinline__ void transpose_body(
    const float* __restrict__ w, __half* __restrict__ o, int K, int N)
{
    __shared__ float t[32][33];
    const int n0 = blockIdx.x * 32, k0 = blockIdx.y * 32;
    const int tx = threadIdx.x, ty = threadIdx.y;
    #pragma unroll
    for (int i = ty; i < 32; i += 8)
        t[i][tx] = w[(size_t)(k0 + i) * N + n0 + tx];
    __syncthreads();
    #pragma unroll
    for (int i = ty; i < 32; i += 8)
        o[(size_t)(n0 + i) * K + k0 + tx] = __float2half(t[tx][i]);
}
__global__ void trans_wa(const float* __restrict__ w) {
    transpose_body(w, g_wa_h, DMODEL, 3 * DMODEL);
}
__global__ void trans_wp(const float* __restrict__ w) {
    transpose_body(w, g_wp_h, DMODEL, DMODEL);
}

// ---------------------------------------------------------------------------
// mma.sync GEMM: C = A(fp16) @ BT(fp16) + bias, single pass.
// CTA 128x128, K-step 64 (16 iters), 8 warps (4 M x 2 N), warp tile 32x64.
// ROWB=144: 128B data + 16B pad -> 16-aligned, conflict-free ldsm phases.
// ---------------------------------------------------------------------------
#define TK      64
#define NSTEP   (GK / TK)         // 16
#define ROWB    144
#define TILEB   (128 * ROWB)      // 18432
#define STAGEB  (2 * TILEB)       // 36864: A, B
#define GSMEM   (2 * STAGEB)      // 73728 -> 2 CTAs/SM

template <int MODE>
__device__ __forceinline__ void gemm_mma_body(
    const __half* __restrict__ A, const __half* __restrict__ BT,
    const float* __restrict__ bias, float* __restrict__ C, int N)
{
    extern __shared__ char smem[];
    const uint32_t sb = smem_to_u32(smem);
    const int tid  = threadIdx.x;
    const int lane = tid & 31;
    const int wid  = tid >> 5;
    const int wm   = wid & 3;
    const int wn   = wid >> 2;
    const int gid  = lane >> 2;
    const int tig  = lane & 3;
    const int m0   = blockIdx.y * 128;
    const int n0   = blockIdx.x * 128;

    float d[2][8][4];
    #pragma unroll
    for (int mt = 0; mt < 2; mt++)
        #pragma unroll
        for (int nt = 0; nt < 8; nt++)
            #pragma unroll
            for (int c = 0; c < 4; c++) d[mt][nt][c] = 0.0f;

    const uint32_t a_off = (uint32_t)((wm * 32 + (lane & 7) + ((lane >> 3) & 1) * 8) * ROWB
                                      + (lane >> 4) * 16);
    const uint32_t b_off = (uint32_t)((wn * 64 + ((lane >> 4) & 1) * 8 + (lane & 7)) * ROWB
                                      + ((lane >> 3) & 1) * 16);

    auto load_stage = [&](int t, int s) {
        const int k0 = t * TK;
        const uint32_t sbase = sb + s * STAGEB;
        #pragma unroll
        for (int i = 0; i < 4; i++) {
            int idx = tid + i * 256;
            int row = idx >> 3;
            int c   = idx & 7;
            const uint32_t so = (uint32_t)(row * ROWB + c * 16);
            CP_ASYNC16(sbase + so,         A  + (size_t)(m0 + row) * GK + k0 + c * 8);
            CP_ASYNC16(sbase + TILEB + so, BT + (size_t)(n0 + row) * GK + k0 + c * 8);
        }
        CP_COMMIT();
    };

    load_stage(0, 0);

    #pragma unroll 1
    for (int t = 0; t < NSTEP; t++) {
        const int b = t & 1;
        CP_WAIT0();
        __syncthreads();
        if (t + 1 < NSTEP) load_stage(t + 1, b ^ 1);

        const uint32_t ah_base = sb + b * STAGEB + a_off;
        const uint32_t bh_base = sb + b * STAGEB + TILEB + b_off;

        #pragma unroll
        for (int kk = 0; kk < 4; kk++) {
            const uint32_t ko = kk * 32;
            uint32_t Af[2][4];
            ldsm_x4(Af[0][0], Af[0][1], Af[0][2], Af[0][3], ah_base + ko);
            ldsm_x4(Af[1][0], Af[1][1], Af[1][2], Af[1][3], ah_base + 16 * ROWB + ko);

            uint32_t Bh[8][2];
            #pragma unroll
            for (int p = 0; p < 4; p++)
                ldsm_x4(Bh[2 * p][0], Bh[2 * p][1], Bh[2 * p + 1][0], Bh[2 * p + 1][1],
                        bh_base + p * 16 * ROWB + ko);

            #pragma unroll
            for (int mt = 0; mt < 2; mt++)
                #pragma unroll
                for (int nt = 0; nt < 8; nt++)
                    mma16816(d[mt][nt], Af[mt], Bh[nt][0], Bh[nt][1]);
        }
    }

    if (MODE == 0) {
        #pragma unroll
        for (int nt = 0; nt < 8; nt++) {
            const int col = n0 + wn * 64 + nt * 8 + tig * 2;
            const float bx = __ldg(&bias[col]);
            const float by = __ldg(&bias[col + 1]);
            #pragma unroll
            for (int mt = 0; mt < 2; mt++) {
                const size_t r0 = (size_t)(m0 + wm * 32 + mt * 16 + gid);
                *(float2*)&C[r0 * N + col] =
                    make_float2(d[mt][nt][0] + bx, d[mt][nt][1] + by);
                *(float2*)&C[(r0 + 8) * N + col] =
                    make_float2(d[mt][nt][2] + bx, d[mt][nt][3] + by);
            }
        }
    } else {
        #pragma unroll
        for (int nt = 0; nt < 8; nt++) {
            const int col = n0 + wn * 64 + nt * 8 + tig * 2;
            const float bx = __ldg(&bias[col]);
            const float by = __ldg(&bias[col + 1]);
            const int sel = col >> 10;
            const float scl = (sel == 0) ? 0.125f : 1.0f;
            __half* dh = (sel == 0) ? g_q_h : (sel == 1) ? g_k_h : g_v_h;
            const int hh = (col >> 6) & 15;
            const int dd = col & 63;
            #pragma unroll
            for (int mt = 0; mt < 2; mt++) {
                const int row = m0 + wm * 32 + mt * 16 + gid;
                const int bb = row >> 11, ss = row & 2047;
                const size_t base = ((size_t)(bb * NHEAD + hh) * SEQ + ss) * HDIM + dd;
                *(uint32_t*)&dh[base] =
                    pack_h2((d[mt][nt][0] + bx) * scl, (d[mt][nt][1] + by) * scl);
                *(uint32_t*)&dh[base + 8 * HDIM] =
                    pack_h2((d[mt][nt][2] + bx) * scl, (d[mt][nt][3] + by) * scl);
            }
        }
    }
}

__global__ __launch_bounds__(256, 2)
void gemm_qkv_mma(const float* __restrict__ bias)
{
    gemm_mma_body<1>(g_x_h, g_wa_h, bias, nullptr, 3 * DMODEL);
}
__global__ __launch_bounds__(256, 2)
void gemm_proj_mma(const float* __restrict__ bias, float* __restrict__ out)
{
    gemm_mma_body<0>(g_ao_h, g_wp_h, bias, out, DMODEL);
}

// ---------------------------------------------------------------------------
// Causal flash attention, single-pass fp16.
// CTA = (128 q rows, bh), 8 warps x m16.
// KV staged 128 rows per barrier, computed as two 64-col halves;
// halves entirely above the diagonal are skipped (warp-uniform).
// ---------------------------------------------------------------------------
#define ASTR   144
#define SQ_H   0
#define AKV0   (128 * ASTR)                    // 18432
#define KVROWS 128
#define KVBUF  (2 * KVROWS * ASTR)             // 36864 (K, V)
#define SKV(s, t) (AKV0 + (s) * KVBUF + (t) * (KVROWS * ASTR))
#define ATT_SMEM (AKV0 + 2 * KVBUF)            // 92160; x2 = 184320 fits

__global__ __launch_bounds__(256, 2)
void attn_mma()
{
    extern __shared__ char smem[];
    const uint32_t sb = smem_to_u32(smem);
    const int tid  = threadIdx.x;
    const int wid  = tid >> 5;
    const int lane = tid & 31;
    const int g    = lane >> 2;
    const int t2   = (lane & 3) * 2;
    const int qi   = (int)(gridDim.x - 1 - blockIdx.x);  // heavy tiles first
    const int bh   = blockIdx.y;
    const int bb   = bh >> 4;
    const int h    = bh & 15;
    const int q0   = qi * 128;
    const int wm0  = wid * 16;

    const size_t head_base = (size_t)bh * SEQ * HDIM;

    // stage loader: 128 rows of K and V (8 x 16B cp.async per thread)
    auto load_kv = [&](int jt, int s) {
        #pragma unroll
        for (int i = 0; i < 8; i++) {
            const int tp  = i >> 2;                  // 0 = K, 1 = V
            const int idx = tid + (i & 3) * 256;     // 0..1023
            const int row = idx >> 3;                // 0..127
            const int c   = idx & 7;
            uint32_t dst = sb + SKV(s, tp) + row * ASTR + c * 16;
            const __half* src = ((tp == 0) ? g_k_h : g_v_h)
                + head_base + (size_t)(jt * KVROWS + row) * HDIM + c * 8;
            CP_ASYNC16(dst, src);
        }
        CP_COMMIT();
    };

    load_kv(0, 0);

    {
        const __half* q_g = g_q_h + head_base + (size_t)q0 * HDIM;
        #pragma unroll
        for (int i = 0; i < 4; i++) {
            int idx = tid + i * 256;
            int row = idx >> 3;
            int c   = idx & 7;
            *(uint4*)(smem + SQ_H + row * ASTR + c * 16) =
                *(const uint4*)(q_g + (size_t)row * HDIM + c * 8);
        }
    }
    CP_WAIT0();
    __syncthreads();

    const uint32_t qaddr = sb + SQ_H +
        (uint32_t)((wm0 + (lane & 7) + ((lane >> 3) & 1) * 8) * ASTR + (lane >> 4) * 16);

    float o[8][4];
    #pragma unroll
    for (int nt = 0; nt < 8; nt++)
        #pragma unroll
        for (int c = 0; c < 4; c++) o[nt][c] = 0.0f;
    float mrun0 = -1e30f, mrun1 = -1e30f, lrun0 = 0.0f, lrun1 = 0.0f;

    const int njt = qi + 1;                    // 128-row staging tiles
    const uint32_t k_off =
        (uint32_t)(((lane & 7) + ((lane >> 4) & 1) * 8) * ASTR + ((lane >> 3) & 1) * 16);
    const uint32_t v_off =
        (uint32_t)(((lane & 7) + ((lane >> 3) & 1) * 8) * ASTR + (lane >> 4) * 16);

    #pragma unroll 1
    for (int jt = 0; jt < njt; jt++) {
        const int bfr = jt & 1;
        CP_WAIT0();
        __syncthreads();
        if (jt + 1 < njt) load_kv(jt + 1, bfr ^ 1);

        #pragma unroll
        for (int hb = 0; hb < 2; hb++) {
            const int col0 = jt * KVROWS + hb * 64;
            if (col0 > q0 + wm0 + 15) continue;   // fully masked (warp-uniform)

            float s[8][4];
            #pragma unroll
            for (int nt = 0; nt < 8; nt++)
                #pragma unroll
                for (int c = 0; c < 4; c++) s[nt][c] = 0.0f;

            const uint32_t kaddr = sb + SKV(bfr, 0) + hb * (64 * ASTR) + k_off;
            #pragma unroll
            for (int kt = 0; kt < 4; kt++) {
                uint32_t qf[4];
                ldsm_x4(qf[0], qf[1], qf[2], qf[3], qaddr + kt * 32);
                #pragma unroll
                for (int np = 0; np < 4; np++) {
                    uint32_t a0, a1, a2, a3;
                    ldsm_x4(a0, a1, a2, a3, kaddr + np * (16 * ASTR) + kt * 32);
                    mma16816(s[2 * np],     qf, a0, a1);
                    mma16816(s[2 * np + 1], qf, a2, a3);
                }
            }

            if (col0 + 63 > q0 + wm0) {
                const int row0 = q0 + wm0 + g;
                #pragma unroll
                for (int nt = 0; nt < 8; nt++) {
                    const int col = col0 + nt * 8 + t2;
                    #pragma unroll
                    for (int c = 0; c < 4; c++) {
                        int cc = col + (c & 1);
                        int rr = row0 + (c >> 1) * 8;
                        if (cc > rr) s[nt][c] = -1e30f;
                    }
                }
            }

            float mt0 = -1e30f, mt1 = -1e30f;
            #pragma unroll
            for (int nt = 0; nt < 8; nt++) {
                mt0 = fmaxf(mt0, fmaxf(s[nt][0], s[nt][1]));
                mt1 = fmaxf(mt1, fmaxf(s[nt][2], s[nt][3]));
            }
            mt0 = fmaxf(mt0, __shfl_xor_sync(0xffffffffu, mt0, 1));
            mt0 = fmaxf(mt0, __shfl_xor_sync(0xffffffffu, mt0, 2));
            mt1 = fmaxf(mt1, __shfl_xor_sync(0xffffffffu, mt1, 1));
            mt1 = fmaxf(mt1, __shfl_xor_sync(0xffffffffu, mt1, 2));

            const float mn0 = fmaxf(mrun0, mt0);
            const float mn1 = fmaxf(mrun1, mt1);
            const float f0 = __expf(mrun0 - mn0);
            const float f1 = __expf(mrun1 - mn1);
            mrun0 = mn0; mrun1 = mn1;

            float lt0 = 0.0f, lt1 = 0.0f;
            #pragma unroll
            for (int nt = 0; nt < 8; nt++) {
                s[nt][0] = __expf(s[nt][0] - mn0); lt0 += s[nt][0];
                s[nt][1] = __expf(s[nt][1] - mn0); lt0 += s[nt][1];
                s[nt][2] = __expf(s[nt][2] - mn1); lt1 += s[nt][2];
                s[nt][3] = __expf(s[nt][3] - mn1); lt1 += s[nt][3];
            }
            lt0 += __shfl_xor_sync(0xffffffffu, lt0, 1);
            lt0 += __shfl_xor_sync(0xffffffffu, lt0, 2);
            lt1 += __shfl_xor_sync(0xffffffffu, lt1, 1);
            lt1 += __shfl_xor_sync(0xffffffffu, lt1, 2);
            lrun0 = lrun0 * f0 + lt0;
            lrun1 = lrun1 * f1 + lt1;
            #pragma unroll
            for (int nt = 0; nt < 8; nt++) {
                o[nt][0] *= f0; o[nt][1] *= f0;
                o[nt][2] *= f1; o[nt][3] *= f1;
            }

            const uint32_t vaddr = sb + SKV(bfr, 1) + hb * (64 * ASTR) + v_off;
            #pragma unroll
            for (int kt = 0; kt < 4; kt++) {
                uint32_t ap[4];
                ap[0] = pack_h2(s[2 * kt][0],     s[2 * kt][1]);
                ap[1] = pack_h2(s[2 * kt][2],     s[2 * kt][3]);
                ap[2] = pack_h2(s[2 * kt + 1][0], s[2 * kt + 1][1]);
                ap[3] = pack_h2(s[2 * kt + 1][2], s[2 * kt + 1][3]);
                #pragma unroll
                for (int np = 0; np < 4; np++) {
                    uint32_t v0, v1, v2, v3;
                    ldsm_x4_t(v0, v1, v2, v3, vaddr + kt * (16 * ASTR) + np * 32);
                    mma16816(o[2 * np],     ap, v0, v1);
                    mma16816(o[2 * np + 1], ap, v2, v3);
                }
            }
        }
    }

    // normalize + write merged-head fp16 (proj A operand)
    const float inv0 = 1.0f / lrun0;
    const float inv1 = 1.0f / lrun1;
    const size_t r0 = (size_t)bb * SEQ + q0 + wm0 + g;
    const int colb = h * HDIM + t2;
    #pragma unroll
    for (int nt = 0; nt < 8; nt++) {
        *(uint32_t*)&g_ao_h[r0 * DMODEL + colb + nt * 8] =
            pack_h2(o[nt][0] * inv0, o[nt][1] * inv0);
        *(uint32_t*)&g_ao_h[(r0 + 8) * DMODEL + colb + nt * 8] =
            pack_h2(o[nt][2] * inv1, o[nt][3] * inv1);
    }
}

// ---------------------------------------------------------------------------
extern "C" void kernel_launch(void* const* d_in, const int* in_sizes, int n_in,
                              void* d_out, int out_size)
{
    const float* x      = (const float*)d_in[0];
    const float* w_attn = (const float*)d_in[1];
    const float* b_attn = (const float*)d_in[2];
    const float* w_proj = (const float*)d_in[3];
    const float* b_proj = (const float*)d_in[4];
    float* out = (float*)d_out;

    cudaFuncSetAttribute(attn_mma,
                         cudaFuncAttributeMaxDynamicSharedMemorySize, ATT_SMEM);
    cudaFuncSetAttribute(gemm_qkv_mma,
                         cudaFuncAttributeMaxDynamicSharedMemorySize, GSMEM);
    cudaFuncSetAttribute(gemm_proj_mma,
                         cudaFuncAttributeMaxDynamicSharedMemorySize, GSMEM);

    split_x<<<MTOT * DMODEL / 1024, 256>>>(x);
    trans_wa<<<dim3(3 * DMODEL / 32, DMODEL / 32), dim3(32, 8)>>>(w_attn);
    trans_wp<<<dim3(DMODEL / 32, DMODEL / 32), dim3(32, 8)>>>(w_proj);

    gemm_qkv_mma<<<dim3(3 * DMODEL / 128, MTOT / 128), 256, GSMEM>>>(b_attn);
    attn_mma<<<dim3(SEQ / 128, BATCH * NHEAD), 256, ATT_SMEM>>>();
    gemm_proj_mma<<<dim3(DMODEL / 128, MTOT / 128), 256, GSMEM>>>(b_proj, out);
}

// round 16
// speedup vs baseline: 2.6918x; 1.0181x over previous
#include <cuda_runtime.h>
#include <cuda_fp16.h>
#include <cstdint>

// ---------------------------------------------------------------------------
// GPT-2 attention block, all-tensor-core, single-pass fp16 mma.sync.
// fp32 accumulate everywhere; fp16 rounding residual ~5e-4 (threshold 1e-3).
//   conv  : x, w_attn, w_proj -> fp16 (elementwise, native layout)
//   qkv   = x @ w_attn + b_attn   (B K-major via ldmatrix.trans; emits q/k/v)
//   att   = causal flash attention (emits att fp16)
//   out   = att @ w_proj + b_proj (fp32 out)
// GEMM: CTA 128x128, warp 32x64, K-step 64 (16 iters), 2-stage, 2 CTAs/SM.
// ---------------------------------------------------------------------------

#define BATCH  4
#define SEQ    2048
#define DMODEL 1024
#define NHEAD  16
#define HDIM   64
#define MTOT   (BATCH * SEQ)
#define GK     1024

__device__ __half g_x_h[(size_t)MTOT * DMODEL];
__device__ __half g_ao_h[(size_t)MTOT * DMODEL];
__device__ __half g_wa_h[DMODEL * 3 * DMODEL];   // [K][N] native layout
__device__ __half g_wp_h[DMODEL * DMODEL];       // [K][N]
#define QKV_ELEMS ((size_t)NHEAD * BATCH * SEQ * HDIM)
__device__ __half g_q_h[QKV_ELEMS];
__device__ __half g_k_h[QKV_ELEMS];
__device__ __half g_v_h[QKV_ELEMS];

// ---------------------------------------------------------------------------
__device__ __forceinline__ uint32_t smem_to_u32(const void* p) {
    uint32_t a;
    asm("{ .reg .u64 t; cvta.to.shared.u64 t, %1; cvt.u32.u64 %0, t; }"
        : "=r"(a) : "l"(p));
    return a;
}
__device__ __forceinline__ void ldsm_x4(uint32_t& r0, uint32_t& r1,
                                        uint32_t& r2, uint32_t& r3, uint32_t a) {
    asm volatile("ldmatrix.sync.aligned.m8n8.x4.shared.b16 {%0,%1,%2,%3}, [%4];"
                 : "=r"(r0), "=r"(r1), "=r"(r2), "=r"(r3) : "r"(a));
}
__device__ __forceinline__ void ldsm_x4_t(uint32_t& r0, uint32_t& r1,
                                          uint32_t& r2, uint32_t& r3, uint32_t a) {
    asm volatile("ldmatrix.sync.aligned.m8n8.x4.trans.shared.b16 {%0,%1,%2,%3}, [%4];"
                 : "=r"(r0), "=r"(r1), "=r"(r2), "=r"(r3) : "r"(a));
}
__device__ __forceinline__ void mma16816(float* d, const uint32_t* a,
                                         uint32_t b0, uint32_t b1) {
    asm volatile(
        "mma.sync.aligned.m16n8k16.row.col.f32.f16.f16.f32 "
        "{%0,%1,%2,%3}, {%4,%5,%6,%7}, {%8,%9}, {%0,%1,%2,%3};"
        : "+f"(d[0]), "+f"(d[1]), "+f"(d[2]), "+f"(d[3])
        : "r"(a[0]), "r"(a[1]), "r"(a[2]), "r"(a[3]), "r"(b0), "r"(b1));
}
#define CP_ASYNC16(dst, src) \
    asm volatile("cp.async.cg.shared.global [%0], [%1], 16;" :: "r"(dst), "l"(src) : "memory")
#define CP_COMMIT() asm volatile("cp.async.commit_group;" ::: "memory")
#define CP_WAIT0()  asm volatile("cp.async.wait_group 0;" ::: "memory")

__device__ __forceinline__ uint32_t pack_h2(float x, float y) {
    __half2 h = __floats2half2_rn(x, y);
    return *(uint32_t*)&h;
}

// ---------------------------------------------------------------------------
// Elementwise fp32 -> fp16 (replaces split_x and both transpose kernels).
// ---------------------------------------------------------------------------
__global__ __launch_bounds__(256)
void conv_h(const float* __restrict__ src, __half* __restrict__ dst)
{
    const size_t i = ((size_t)blockIdx.x * 256 + threadIdx.x) * 4;
    float4 v = *(const float4*)(src + i);
    *(uint2*)&dst[i] = make_uint2(pack_h2(v.x, v.y), pack_h2(v.z, v.w));
}

// ---------------------------------------------------------------------------
// mma.sync GEMM: C = A(fp16) @ W(fp16, K-major) + bias, single pass.
// A fragments via ldmatrix; B fragments via ldmatrix.trans from K-major tile.
// CTA 128x128, K-step 64 (16 iters), 8 warps (4 M x 2 N), warp tile 32x64.
// ---------------------------------------------------------------------------
#define TK      64
#define NSTEP   (GK / TK)           // 16
#define AROWB   144                 // A row: 128B data + 16B pad
#define BROWB   272                 // B row: 256B data + 16B pad
#define ATILEB  (128 * AROWB)       // 18432
#define BTILEB  (TK * BROWB)        // 17408
#define STAGEB  (ATILEB + BTILEB)   // 35840
#define GSMEM   (2 * STAGEB)        // 71680 -> 2 CTAs/SM

template <int MODE>
__device__ __forceinline__ void gemm_mma_body(
    const __half* __restrict__ A, const __half* __restrict__ W,
    const float* __restrict__ bias, float* __restrict__ C, int N)
{
    extern __shared__ char smem[];
    const uint32_t sb = smem_to_u32(smem);
    const int tid  = threadIdx.x;
    const int lane = tid & 31;
    const int wid  = tid >> 5;
    const int wm   = wid & 3;
    const int wn   = wid >> 2;
    const int gid  = lane >> 2;
    const int tig  = lane & 3;
    const int m0   = blockIdx.y * 128;
    const int n0   = blockIdx.x * 128;

    float d[2][8][4];
    #pragma unroll
    for (int mt = 0; mt < 2; mt++)
        #pragma unroll
        for (int nt = 0; nt < 8; nt++)
            #pragma unroll
            for (int c = 0; c < 4; c++) d[mt][nt][c] = 0.0f;

    const uint32_t a_off = (uint32_t)((wm * 32 + (lane & 7) + ((lane >> 3) & 1) * 8) * AROWB
                                      + (lane >> 4) * 16);
    // B (trans) lane address: rows = k, cols = n; same pattern as attn PV.
    const uint32_t b_off = (uint32_t)(((lane & 7) + ((lane >> 3) & 1) * 8) * BROWB
                                      + (lane >> 4) * 16 + wn * 128);

    auto load_stage = [&](int t, int s) {
        const int k0 = t * TK;
        const uint32_t sbase = sb + s * STAGEB;
        // A: 128 rows x 8 chunks (16B), 4 per thread
        #pragma unroll
        for (int i = 0; i < 4; i++) {
            int idx = tid + i * 256;
            int row = idx >> 3;
            int c   = idx & 7;
            CP_ASYNC16(sbase + (uint32_t)(row * AROWB + c * 16),
                       A + (size_t)(m0 + row) * GK + k0 + c * 8);
        }
        // B: 64 k-rows x 16 chunks (16B), 4 per thread, K-major from W
        #pragma unroll
        for (int i = 0; i < 4; i++) {
            int idx = tid + i * 256;
            int row = idx >> 4;           // 0..63
            int c   = idx & 15;           // 0..15
            CP_ASYNC16(sbase + ATILEB + (uint32_t)(row * BROWB + c * 16),
                       W + (size_t)(k0 + row) * N + n0 + c * 8);
        }
        CP_COMMIT();
    };

    load_stage(0, 0);

    #pragma unroll 1
    for (int t = 0; t < NSTEP; t++) {
        const int b = t & 1;
        CP_WAIT0();
        __syncthreads();
        if (t + 1 < NSTEP) load_stage(t + 1, b ^ 1);

        const uint32_t ah_base = sb + b * STAGEB + a_off;
        const uint32_t bt_base = sb + b * STAGEB + ATILEB + b_off;

        #pragma unroll
        for (int kk = 0; kk < 4; kk++) {
            const uint32_t ko = kk * 32;
            uint32_t Af[2][4];
            ldsm_x4(Af[0][0], Af[0][1], Af[0][2], Af[0][3], ah_base + ko);
            ldsm_x4(Af[1][0], Af[1][1], Af[1][2], Af[1][3], ah_base + 16 * AROWB + ko);

            uint32_t Bh[8][2];
            #pragma unroll
            for (int np = 0; np < 4; np++)
                ldsm_x4_t(Bh[2 * np][0], Bh[2 * np][1],
                          Bh[2 * np + 1][0], Bh[2 * np + 1][1],
                          bt_base + kk * (16 * BROWB) + np * 32);

            #pragma unroll
            for (int mt = 0; mt < 2; mt++)
                #pragma unroll
                for (int nt = 0; nt < 8; nt++)
                    mma16816(d[mt][nt], Af[mt], Bh[nt][0], Bh[nt][1]);
        }
    }

    if (MODE == 0) {
        #pragma unroll
        for (int nt = 0; nt < 8; nt++) {
            const int col = n0 + wn * 64 + nt * 8 + tig * 2;
            const float bx = __ldg(&bias[col]);
            const float by = __ldg(&bias[col + 1]);
            #pragma unroll
            for (int mt = 0; mt < 2; mt++) {
                const size_t r0 = (size_t)(m0 + wm * 32 + mt * 16 + gid);
                *(float2*)&C[r0 * N + col] =
                    make_float2(d[mt][nt][0] + bx, d[mt][nt][1] + by);
                *(float2*)&C[(r0 + 8) * N + col] =
                    make_float2(d[mt][nt][2] + bx, d[mt][nt][3] + by);
            }
        }
    } else {
        // qkv epilogue: q -> fp16 scaled 1/8, k/v -> fp16, head-separated
        #pragma unroll
        for (int nt = 0; nt < 8; nt++) {
            const int col = n0 + wn * 64 + nt * 8 + tig * 2;
            const float bx = __ldg(&bias[col]);
            const float by = __ldg(&bias[col + 1]);
            const int sel = col >> 10;
            const float scl = (sel == 0) ? 0.125f : 1.0f;
            __half* dh = (sel == 0) ? g_q_h : (sel == 1) ? g_k_h : g_v_h;
            const int hh = (col >> 6) & 15;
            const int dd = col & 63;
            #pragma unroll
            for (int mt = 0; mt < 2; mt++) {
                const int row = m0 + wm * 32 + mt * 16 + gid;
                const int bb = row >> 11, ss = row & 2047;
                const size_t base = ((size_t)(bb * NHEAD + hh) * SEQ + ss) * HDIM + dd;
                *(uint32_t*)&dh[base] =
                    pack_h2((d[mt][nt][0] + bx) * scl, (d[mt][nt][1] + by) * scl);
                *(uint32_t*)&dh[base + 8 * HDIM] =
                    pack_h2((d[mt][nt][2] + bx) * scl, (d[mt][nt][3] + by) * scl);
            }
        }
    }
}

__global__ __launch_bounds__(256, 2)
void gemm_qkv_mma(const float* __restrict__ bias)
{
    gemm_mma_body<1>(g_x_h, g_wa_h, bias, nullptr, 3 * DMODEL);
}
__global__ __launch_bounds__(256, 2)
void gemm_proj_mma(const float* __restrict__ bias, float* __restrict__ out)
{
    gemm_mma_body<0>(g_ao_h, g_wp_h, bias, out, DMODEL);
}

// ---------------------------------------------------------------------------
// Causal flash attention, single-pass fp16 (round-15 structure).
// CTA = (128 q rows, bh), 8 warps x m16.
// KV staged 128 rows/barrier, two 64-col halves; masked halves skipped.
// ---------------------------------------------------------------------------
#define ASTR   144
#define SQ_H   0
#define AKV0   (128 * ASTR)
#define KVROWS 128
#define KVBUF  (2 * KVROWS * ASTR)
#define SKV(s, t) (AKV0 + (s) * KVBUF + (t) * (KVROWS * ASTR))
#define ATT_SMEM (AKV0 + 2 * KVBUF)            // 92160; x2 = 184320 fits

__global__ __launch_bounds__(256, 2)
void attn_mma()
{
    extern __shared__ char smem[];
    const uint32_t sb = smem_to_u32(smem);
    const int tid  = threadIdx.x;
    const int wid  = tid >> 5;
    const int lane = tid & 31;
    const int g    = lane >> 2;
    const int t2   = (lane & 3) * 2;
    const int qi   = (int)(gridDim.x - 1 - blockIdx.x);
    const int bh   = blockIdx.y;
    const int bb   = bh >> 4;
    const int h    = bh & 15;
    const int q0   = qi * 128;
    const int wm0  = wid * 16;

    const size_t head_base = (size_t)bh * SEQ * HDIM;

    auto load_kv = [&](int jt, int s) {
        #pragma unroll
        for (int i = 0; i < 8; i++) {
            const int tp  = i >> 2;
            const int idx = tid + (i & 3) * 256;
            const int row = idx >> 3;
            const int c   = idx & 7;
            uint32_t dst = sb + SKV(s, tp) + row * ASTR + c * 16;
            const __half* src = ((tp == 0) ? g_k_h : g_v_h)
                + head_base + (size_t)(jt * KVROWS + row) * HDIM + c * 8;
            CP_ASYNC16(dst, src);
        }
        CP_COMMIT();
    };

    load_kv(0, 0);

    {
        const __half* q_g = g_q_h + head_base + (size_t)q0 * HDIM;
        #pragma unroll
        for (int i = 0; i < 4; i++) {
            int idx = tid + i * 256;
            int row = idx >> 3;
            int c   = idx & 7;
            *(uint4*)(smem + SQ_H + row * ASTR + c * 16) =
                *(const uint4*)(q_g + (size_t)row * HDIM + c * 8);
        }
    }
    CP_WAIT0();
    __syncthreads();

    const uint32_t qaddr = sb + SQ_H +
        (uint32_t)((wm0 + (lane & 7) + ((lane >> 3) & 1) * 8) * ASTR + (lane >> 4) * 16);

    float o[8][4];
    #pragma unroll
    for (int nt = 0; nt < 8; nt++)
        #pragma unroll
        for (int c = 0; c < 4; c++) o[nt][c] = 0.0f;
    float mrun0 = -1e30f, mrun1 = -1e30f, lrun0 = 0.0f, lrun1 = 0.0f;

    const int njt = qi + 1;
    const uint32_t k_off =
        (uint32_t)(((lane & 7) + ((lane >> 4) & 1) * 8) * ASTR + ((lane >> 3) & 1) * 16);
    const uint32_t v_off =
        (uint32_t)(((lane & 7) + ((lane >> 3) & 1) * 8) * ASTR + (lane >> 4) * 16);

    #pragma unroll 1
    for (int jt = 0; jt < njt; jt++) {
        const int bfr = jt & 1;
        CP_WAIT0();
        __syncthreads();
        if (jt + 1 < njt) load_kv(jt + 1, bfr ^ 1);

        #pragma unroll
        for (int hb = 0; hb < 2; hb++) {
            const int col0 = jt * KVROWS + hb * 64;
            if (col0 > q0 + wm0 + 15) continue;

            float s[8][4];
            #pragma unroll
            for (int nt = 0; nt < 8; nt++)
                #pragma unroll
                for (int c = 0; c < 4; c++) s[nt][c] = 0.0f;

            const uint32_t kaddr = sb + SKV(bfr, 0) + hb * (64 * ASTR) + k_off;
            #pragma unroll
            for (int kt = 0; kt < 4; kt++) {
                uint32_t qf[4];
                ldsm_x4(qf[0], qf[1], qf[2], qf[3], qaddr + kt * 32);
                #pragma unroll
                for (int np = 0; np < 4; np++) {
                    uint32_t a0, a1, a2, a3;
                    ldsm_x4(a0, a1, a2, a3, kaddr + np * (16 * ASTR) + kt * 32);
                    mma16816(s[2 * np],     qf, a0, a1);
                    mma16816(s[2 * np + 1], qf, a2, a3);
                }
            }

            if (col0 + 63 > q0 + wm0) {
                const int row0 = q0 + wm0 + g;
                #pragma unroll
                for (int nt = 0; nt < 8; nt++) {
                    const int col = col0 + nt * 8 + t2;
                    #pragma unroll
                    for (int c = 0; c < 4; c++) {
                        int cc = col + (c & 1);
                        int rr = row0 + (c >> 1) * 8;
                        if (cc > rr) s[nt][c] = -1e30f;
                    }
                }
            }

            float mt0 = -1e30f, mt1 = -1e30f;
            #pragma unroll
            for (int nt = 0; nt < 8; nt++) {
                mt0 = fmaxf(mt0, fmaxf(s[nt][0], s[nt][1]));
                mt1 = fmaxf(mt1, fmaxf(s[nt][2], s[nt][3]));
            }
            mt0 = fmaxf(mt0, __shfl_xor_sync(0xffffffffu, mt0, 1));
            mt0 = fmaxf(mt0, __shfl_xor_sync(0xffffffffu, mt0, 2));
            mt1 = fmaxf(mt1, __shfl_xor_sync(0xffffffffu, mt1, 1));
            mt1 = fmaxf(mt1, __shfl_xor_sync(0xffffffffu, mt1, 2));

            const float mn0 = fmaxf(mrun0, mt0);
            const float mn1 = fmaxf(mrun1, mt1);
            const float f0 = __expf(mrun0 - mn0);
            const float f1 = __expf(mrun1 - mn1);
            mrun0 = mn0; mrun1 = mn1;

            float lt0 = 0.0f, lt1 = 0.0f;
            #pragma unroll
            for (int nt = 0; nt < 8; nt++) {
                s[nt][0] = __expf(s[nt][0] - mn0); lt0 += s[nt][0];
                s[nt][1] = __expf(s[nt][1] - mn0); lt0 += s[nt][1];
                s[nt][2] = __expf(s[nt][2] - mn1); lt1 += s[nt][2];
                s[nt][3] = __expf(s[nt][3] - mn1); lt1 += s[nt][3];
            }
            lt0 += __shfl_xor_sync(0xffffffffu, lt0, 1);
            lt0 += __shfl_xor_sync(0xffffffffu, lt0, 2);
            lt1 += __shfl_xor_sync(0xffffffffu, lt1, 1);
            lt1 += __shfl_xor_sync(0xffffffffu, lt1, 2);
            lrun0 = lrun0 * f0 + lt0;
            lrun1 = lrun1 * f1 + lt1;
            #pragma unroll
            for (int nt = 0; nt < 8; nt++) {
                o[nt][0] *= f0; o[nt][1] *= f0;
                o[nt][2] *= f1; o[nt][3] *= f1;
            }

            const uint32_t vaddr = sb + SKV(bfr, 1) + hb * (64 * ASTR) + v_off;
            #pragma unroll
            for (int kt = 0; kt < 4; kt++) {
                uint32_t ap[4];
                ap[0] = pack_h2(s[2 * kt][0],     s[2 * kt][1]);
                ap[1] = pack_h2(s[2 * kt][2],     s[2 * kt][3]);
                ap[2] = pack_h2(s[2 * kt + 1][0], s[2 * kt + 1][1]);
                ap[3] = pack_h2(s[2 * kt + 1][2], s[2 * kt + 1][3]);
                #pragma unroll
                for (int np = 0; np < 4; np++) {
                    uint32_t v0, v1, v2, v3;
                    ldsm_x4_t(v0, v1, v2, v3, vaddr + kt * (16 * ASTR) + np * 32);
                    mma16816(o[2 * np],     ap, v0, v1);
                    mma16816(o[2 * np + 1], ap, v2, v3);
                }
            }
        }
    }

    const float inv0 = 1.0f / lrun0;
    const float inv1 = 1.0f / lrun1;
    const size_t r0 = (size_t)bb * SEQ + q0 + wm0 + g;
    const int colb = h * HDIM + t2;
    #pragma unroll
    for (int nt = 0; nt < 8; nt++) {
        *(uint32_t*)&g_ao_h[r0 * DMODEL + colb + nt * 8] =
            pack_h2(o[nt][0] * inv0, o[nt][1] * inv0);
        *(uint32_t*)&g_ao_h[(r0 + 8) * DMODEL + colb + nt * 8] =
            pack_h2(o[nt][2] * inv1, o[nt][3] * inv1);
    }
}

// ---------------------------------------------------------------------------
extern "C" void kernel_launch(void* const* d_in, const int* in_sizes, int n_in,
                              void* d_out, int out_size)
{
    const float* x      = (const float*)d_in[0];
    const float* w_attn = (const float*)d_in[1];
    const float* b_attn = (const float*)d_in[2];
    const float* w_proj = (const float*)d_in[3];
    const float* b_proj = (const float*)d_in[4];
    float* out = (float*)d_out;

    cudaFuncSetAttribute(attn_mma,
                         cudaFuncAttributeMaxDynamicSharedMemorySize, ATT_SMEM);
    cudaFuncSetAttribute(gemm_qkv_mma,
                         cudaFuncAttributeMaxDynamicSharedMemorySize, GSMEM);
    cudaFuncSetAttribute(gemm_proj_mma,
                         cudaFuncAttributeMaxDynamicSharedMemorySize, GSMEM);

    __half* d_xh;  cudaGetSymbolAddress((void**)&d_xh, g_x_h);
    __half* d_wah; cudaGetSymbolAddress((void**)&d_wah, g_wa_h);
    __half* d_wph; cudaGetSymbolAddress((void**)&d_wph, g_wp_h);

    conv_h<<<MTOT * DMODEL / 1024, 256>>>(x, d_xh);
    conv_h<<<3 * DMODEL * DMODEL / 1024, 256>>>(w_attn, d_wah);
    conv_h<<<DMODEL * DMODEL / 1024, 256>>>(w_proj, d_wph);

    gemm_qkv_mma<<<dim3(3 * DMODEL / 128, MTOT / 128), 256, GSMEM>>>(b_attn);
    attn_mma<<<dim3(SEQ / 128, BATCH * NHEAD), 256, ATT_SMEM>>>();
    gemm_proj_mma<<<dim3(DMODEL / 128, MTOT / 128), 256, GSMEM>>>(b_proj, out);
}

// round 17
// speedup vs baseline: 2.7294x; 1.0140x over previous
#include <cuda_runtime.h>
#include <cuda_fp16.h>
#include <cstdint>

// ---------------------------------------------------------------------------
// GPT-2 attention block, all-tensor-core, single-pass fp16 mma.sync.
// fp32 accumulate everywhere; fp16 rounding residual ~5e-4 (threshold 1e-3).
//   conv  : x, w_attn, w_proj -> fp16 (ONE fused elementwise launch)
//   qkv   = x @ w_attn + b_attn   (B K-major via ldmatrix.trans; emits q/k/v)
//   att   = causal flash attention (emits att fp16)
//   out   = att @ w_proj + b_proj (fp32 out)
// GEMM: CTA 128x128, warp 32x64, K-step 64 (16 iters), 2-stage, 2 CTAs/SM.
// ---------------------------------------------------------------------------

#define BATCH  4
#define SEQ    2048
#define DMODEL 1024
#define NHEAD  16
#define HDIM   64
#define MTOT   (BATCH * SEQ)
#define GK     1024

__device__ __half g_x_h[(size_t)MTOT * DMODEL];
__device__ __half g_ao_h[(size_t)MTOT * DMODEL];
__device__ __half g_wa_h[DMODEL * 3 * DMODEL];   // [K][N] native layout
__device__ __half g_wp_h[DMODEL * DMODEL];       // [K][N]
#define QKV_ELEMS ((size_t)NHEAD * BATCH * SEQ * HDIM)
__device__ __half g_q_h[QKV_ELEMS];
__device__ __half g_k_h[QKV_ELEMS];
__device__ __half g_v_h[QKV_ELEMS];

// ---------------------------------------------------------------------------
__device__ __forceinline__ uint32_t smem_to_u32(const void* p) {
    uint32_t a;
    asm("{ .reg .u64 t; cvta.to.shared.u64 t, %1; cvt.u32.u64 %0, t; }"
        : "=r"(a) : "l"(p));
    return a;
}
__device__ __forceinline__ void ldsm_x4(uint32_t& r0, uint32_t& r1,
                                        uint32_t& r2, uint32_t& r3, uint32_t a) {
    asm volatile("ldmatrix.sync.aligned.m8n8.x4.shared.b16 {%0,%1,%2,%3}, [%4];"
                 : "=r"(r0), "=r"(r1), "=r"(r2), "=r"(r3) : "r"(a));
}
__device__ __forceinline__ void ldsm_x4_t(uint32_t& r0, uint32_t& r1,
                                          uint32_t& r2, uint32_t& r3, uint32_t a) {
    asm volatile("ldmatrix.sync.aligned.m8n8.x4.trans.shared.b16 {%0,%1,%2,%3}, [%4];"
                 : "=r"(r0), "=r"(r1), "=r"(r2), "=r"(r3) : "r"(a));
}
__device__ __forceinline__ void mma16816(float* d, const uint32_t* a,
                                         uint32_t b0, uint32_t b1) {
    asm volatile(
        "mma.sync.aligned.m16n8k16.row.col.f32.f16.f16.f32 "
        "{%0,%1,%2,%3}, {%4,%5,%6,%7}, {%8,%9}, {%0,%1,%2,%3};"
        : "+f"(d[0]), "+f"(d[1]), "+f"(d[2]), "+f"(d[3])
        : "r"(a[0]), "r"(a[1]), "r"(a[2]), "r"(a[3]), "r"(b0), "r"(b1));
}
#define CP_ASYNC16(dst, src) \
    asm volatile("cp.async.cg.shared.global [%0], [%1], 16;" :: "r"(dst), "l"(src) : "memory")
#define CP_COMMIT() asm volatile("cp.async.commit_group;" ::: "memory")
#define CP_WAIT0()  asm volatile("cp.async.wait_group 0;" ::: "memory")

__device__ __forceinline__ uint32_t pack_h2(float x, float y) {
    __half2 h = __floats2half2_rn(x, y);
    return *(uint32_t*)&h;
}

// ---------------------------------------------------------------------------
// Fused elementwise fp32 -> fp16 for x, w_attn, w_proj (one launch).
// ---------------------------------------------------------------------------
#define NX  ((size_t)MTOT * DMODEL)            // 8388608
#define NWA ((size_t)DMODEL * 3 * DMODEL)      // 3145728
#define NWP ((size_t)DMODEL * DMODEL)          // 1048576
#define NTOT (NX + NWA + NWP)                  // 12582912 (/1024 = 12288 blocks)

__global__ __launch_bounds__(256)
void conv_all(const float* __restrict__ x, const float* __restrict__ wa,
              const float* __restrict__ wp)
{
    const size_t i = ((size_t)blockIdx.x * 256 + threadIdx.x) * 4;
    const float* src;
    __half* dst;
    size_t off;
    if (i < NX)            { src = x;  dst = g_x_h;  off = i; }
    else if (i < NX + NWA) { src = wa; dst = g_wa_h; off = i - NX; }
    else                   { src = wp; dst = g_wp_h; off = i - NX - NWA; }
    float4 v = *(const float4*)(src + off);
    *(uint2*)&dst[off] = make_uint2(pack_h2(v.x, v.y), pack_h2(v.z, v.w));
}

// ---------------------------------------------------------------------------
// mma.sync GEMM: C = A(fp16) @ W(fp16, K-major) + bias, single pass.
// A fragments via ldmatrix; B fragments via ldmatrix.trans from K-major tile.
// CTA 128x128, K-step 64 (16 iters), 8 warps (4 M x 2 N), warp tile 32x64.
// ---------------------------------------------------------------------------
#define TK      64
#define NSTEP   (GK / TK)           // 16
#define AROWB   144                 // A row: 128B data + 16B pad
#define BROWB   272                 // B row: 256B data + 16B pad
#define ATILEB  (128 * AROWB)       // 18432
#define BTILEB  (TK * BROWB)        // 17408
#define STAGEB  (ATILEB + BTILEB)   // 35840
#define GSMEM   (2 * STAGEB)        // 71680 -> 2 CTAs/SM

template <int MODE>
__device__ __forceinline__ void gemm_mma_body(
    const __half* __restrict__ A, const __half* __restrict__ W,
    const float* __restrict__ bias, float* __restrict__ C, int N)
{
    extern __shared__ char smem[];
    const uint32_t sb = smem_to_u32(smem);
    const int tid  = threadIdx.x;
    const int lane = tid & 31;
    const int wid  = tid >> 5;
    const int wm   = wid & 3;
    const int wn   = wid >> 2;
    const int gid  = lane >> 2;
    const int tig  = lane & 3;
    const int m0   = blockIdx.y * 128;
    const int n0   = blockIdx.x * 128;

    float d[2][8][4];
    #pragma unroll
    for (int mt = 0; mt < 2; mt++)
        #pragma unroll
        for (int nt = 0; nt < 8; nt++)
            #pragma unroll
            for (int c = 0; c < 4; c++) d[mt][nt][c] = 0.0f;

    const uint32_t a_off = (uint32_t)((wm * 32 + (lane & 7) + ((lane >> 3) & 1) * 8) * AROWB
                                      + (lane >> 4) * 16);
    const uint32_t b_off = (uint32_t)(((lane & 7) + ((lane >> 3) & 1) * 8) * BROWB
                                      + (lane >> 4) * 16 + wn * 128);

    auto load_stage = [&](int t, int s) {
        const int k0 = t * TK;
        const uint32_t sbase = sb + s * STAGEB;
        #pragma unroll
        for (int i = 0; i < 4; i++) {
            int idx = tid + i * 256;
            int row = idx >> 3;
            int c   = idx & 7;
            CP_ASYNC16(sbase + (uint32_t)(row * AROWB + c * 16),
                       A + (size_t)(m0 + row) * GK + k0 + c * 8);
        }
        #pragma unroll
        for (int i = 0; i < 4; i++) {
            int idx = tid + i * 256;
            int row = idx >> 4;
            int c   = idx & 15;
            CP_ASYNC16(sbase + ATILEB + (uint32_t)(row * BROWB + c * 16),
                       W + (size_t)(k0 + row) * N + n0 + c * 8);
        }
        CP_COMMIT();
    };

    load_stage(0, 0);

    #pragma unroll 1
    for (int t = 0; t < NSTEP; t++) {
        const int b = t & 1;
        CP_WAIT0();
        __syncthreads();
        if (t + 1 < NSTEP) load_stage(t + 1, b ^ 1);

        const uint32_t ah_base = sb + b * STAGEB + a_off;
        const uint32_t bt_base = sb + b * STAGEB + ATILEB + b_off;

        #pragma unroll
        for (int kk = 0; kk < 4; kk++) {
            const uint32_t ko = kk * 32;
            uint32_t Af[2][4];
            ldsm_x4(Af[0][0], Af[0][1], Af[0][2], Af[0][3], ah_base + ko);
            ldsm_x4(Af[1][0], Af[1][1], Af[1][2], Af[1][3], ah_base + 16 * AROWB + ko);

            uint32_t Bh[8][2];
            #pragma unroll
            for (int np = 0; np < 4; np++)
                ldsm_x4_t(Bh[2 * np][0], Bh[2 * np][1],
                          Bh[2 * np + 1][0], Bh[2 * np + 1][1],
                          bt_base + kk * (16 * BROWB) + np * 32);

            #pragma unroll
            for (int mt = 0; mt < 2; mt++)
                #pragma unroll
                for (int nt = 0; nt < 8; nt++)
                    mma16816(d[mt][nt], Af[mt], Bh[nt][0], Bh[nt][1]);
        }
    }

    if (MODE == 0) {
        #pragma unroll
        for (int nt = 0; nt < 8; nt++) {
            const int col = n0 + wn * 64 + nt * 8 + tig * 2;
            const float bx = __ldg(&bias[col]);
            const float by = __ldg(&bias[col + 1]);
            #pragma unroll
            for (int mt = 0; mt < 2; mt++) {
                const size_t r0 = (size_t)(m0 + wm * 32 + mt * 16 + gid);
                *(float2*)&C[r0 * N + col] =
                    make_float2(d[mt][nt][0] + bx, d[mt][nt][1] + by);
                *(float2*)&C[(r0 + 8) * N + col] =
                    make_float2(d[mt][nt][2] + bx, d[mt][nt][3] + by);
            }
        }
    } else {
        #pragma unroll
        for (int nt = 0; nt < 8; nt++) {
            const int col = n0 + wn * 64 + nt * 8 + tig * 2;
            const float bx = __ldg(&bias[col]);
            const float by = __ldg(&bias[col + 1]);
            const int sel = col >> 10;
            const float scl = (sel == 0) ? 0.125f : 1.0f;
            __half* dh = (sel == 0) ? g_q_h : (sel == 1) ? g_k_h : g_v_h;
            const int hh = (col >> 6) & 15;
            const int dd = col & 63;
            #pragma unroll
            for (int mt = 0; mt < 2; mt++) {
                const int row = m0 + wm * 32 + mt * 16 + gid;
                const int bb = row >> 11, ss = row & 2047;
                const size_t base = ((size_t)(bb * NHEAD + hh) * SEQ + ss) * HDIM + dd;
                *(uint32_t*)&dh[base] =
                    pack_h2((d[mt][nt][0] + bx) * scl, (d[mt][nt][1] + by) * scl);
                *(uint32_t*)&dh[base + 8 * HDIM] =
                    pack_h2((d[mt][nt][2] + bx) * scl, (d[mt][nt][3] + by) * scl);
            }
        }
    }
}

__global__ __launch_bounds__(256, 2)
void gemm_qkv_mma(const float* __restrict__ bias)
{
    gemm_mma_body<1>(g_x_h, g_wa_h, bias, nullptr, 3 * DMODEL);
}
__global__ __launch_bounds__(256, 2)
void gemm_proj_mma(const float* __restrict__ bias, float* __restrict__ out)
{
    gemm_mma_body<0>(g_ao_h, g_wp_h, bias, out, DMODEL);
}

// ---------------------------------------------------------------------------
// Causal flash attention, single-pass fp16.
// CTA = (128 q rows, bh), 8 warps x m16.
// KV staged 128 rows/barrier, two 64-col halves; masked halves skipped.
// ---------------------------------------------------------------------------
#define ASTR   144
#define SQ_H   0
#define AKV0   (128 * ASTR)
#define KVROWS 128
#define KVBUF  (2 * KVROWS * ASTR)
#define SKV(s, t) (AKV0 + (s) * KVBUF + (t) * (KVROWS * ASTR))
#define ATT_SMEM (AKV0 + 2 * KVBUF)            // 92160; x2 = 184320 fits

__global__ __launch_bounds__(256, 2)
void attn_mma()
{
    extern __shared__ char smem[];
    const uint32_t sb = smem_to_u32(smem);
    const int tid  = threadIdx.x;
    const int wid  = tid >> 5;
    const int lane = tid & 31;
    const int g    = lane >> 2;
    const int t2   = (lane & 3) * 2;
    const int qi   = (int)(gridDim.x - 1 - blockIdx.x);
    const int bh   = blockIdx.y;
    const int bb   = bh >> 4;
    const int h    = bh & 15;
    const int q0   = qi * 128;
    const int wm0  = wid * 16;

    const size_t head_base = (size_t)bh * SEQ * HDIM;

    auto load_kv = [&](int jt, int s) {
        #pragma unroll
        for (int i = 0; i < 8; i++) {
            const int tp  = i >> 2;
            const int idx = tid + (i & 3) * 256;
            const int row = idx >> 3;
            const int c   = idx & 7;
            uint32_t dst = sb + SKV(s, tp) + row * ASTR + c * 16;
            const __half* src = ((tp == 0) ? g_k_h : g_v_h)
                + head_base + (size_t)(jt * KVROWS + row) * HDIM + c * 8;
            CP_ASYNC16(dst, src);
        }
        CP_COMMIT();
    };

    load_kv(0, 0);

    {
        const __half* q_g = g_q_h + head_base + (size_t)q0 * HDIM;
        #pragma unroll
        for (int i = 0; i < 4; i++) {
            int idx = tid + i * 256;
            int row = idx >> 3;
            int c   = idx & 7;
            *(uint4*)(smem + SQ_H + row * ASTR + c * 16) =
                *(const uint4*)(q_g + (size_t)row * HDIM + c * 8);
        }
    }
    CP_WAIT0();
    __syncthreads();

    const uint32_t qaddr = sb + SQ_H +
        (uint32_t)((wm0 + (lane & 7) + ((lane >> 3) & 1) * 8) * ASTR + (lane >> 4) * 16);

    float o[8][4];
    #pragma unroll
    for (int nt = 0; nt < 8; nt++)
        #pragma unroll
        for (int c = 0; c < 4; c++) o[nt][c] = 0.0f;
    float mrun0 = -1e30f, mrun1 = -1e30f, lrun0 = 0.0f, lrun1 = 0.0f;

    const int njt = qi + 1;
    const uint32_t k_off =
        (uint32_t)(((lane & 7) + ((lane >> 4) & 1) * 8) * ASTR + ((lane >> 3) & 1) * 16);
    const uint32_t v_off =
        (uint32_t)(((lane & 7) + ((lane >> 3) & 1) * 8) * ASTR + (lane >> 4) * 16);

    #pragma unroll 1
    for (int jt = 0; jt < njt; jt++) {
        const int bfr = jt & 1;
        CP_WAIT0();
        __syncthreads();
        if (jt + 1 < njt) load_kv(jt + 1, bfr ^ 1);

        #pragma unroll
        for (int hb = 0; hb < 2; hb++) {
            const int col0 = jt * KVROWS + hb * 64;
            if (col0 > q0 + wm0 + 15) continue;

            float s[8][4];
            #pragma unroll
            for (int nt = 0; nt < 8; nt++)
                #pragma unroll
                for (int c = 0; c < 4; c++) s[nt][c] = 0.0f;

            const uint32_t kaddr = sb + SKV(bfr, 0) + hb * (64 * ASTR) + k_off;
            #pragma unroll
            for (int kt = 0; kt < 4; kt++) {
                uint32_t qf[4];
                ldsm_x4(qf[0], qf[1], qf[2], qf[3], qaddr + kt * 32);
                #pragma unroll
                for (int np = 0; np < 4; np++) {
                    uint32_t a0, a1, a2, a3;
                    ldsm_x4(a0, a1, a2, a3, kaddr + np * (16 * ASTR) + kt * 32);
                    mma16816(s[2 * np],     qf, a0, a1);
                    mma16816(s[2 * np + 1], qf, a2, a3);
                }
            }

            if (col0 + 63 > q0 + wm0) {
                const int row0 = q0 + wm0 + g;
                #pragma unroll
                for (int nt = 0; nt < 8; nt++) {
                    const int col = col0 + nt * 8 + t2;
                    #pragma unroll
                    for (int c = 0; c < 4; c++) {
                        int cc = col + (c & 1);
                        int rr = row0 + (c >> 1) * 8;
                        if (cc > rr) s[nt][c] = -1e30f;
                    }
                }
            }

            float mt0 = -1e30f, mt1 = -1e30f;
            #pragma unroll
            for (int nt = 0; nt < 8; nt++) {
                mt0 = fmaxf(mt0, fmaxf(s[nt][0], s[nt][1]));
                mt1 = fmaxf(mt1, fmaxf(s[nt][2], s[nt][3]));
            }
            mt0 = fmaxf(mt0, __shfl_xor_sync(0xffffffffu, mt0, 1));
            mt0 = fmaxf(mt0, __shfl_xor_sync(0xffffffffu, mt0, 2));
            mt1 = fmaxf(mt1, __shfl_xor_sync(0xffffffffu, mt1, 1));
            mt1 = fmaxf(mt1, __shfl_xor_sync(0xffffffffu, mt1, 2));

            const float mn0 = fmaxf(mrun0, mt0);
            const float mn1 = fmaxf(mrun1, mt1);
            const float f0 = __expf(mrun0 - mn0);
            const float f1 = __expf(mrun1 - mn1);
            mrun0 = mn0; mrun1 = mn1;

            float lt0 = 0.0f, lt1 = 0.0f;
            #pragma unroll
            for (int nt = 0; nt < 8; nt++) {
                s[nt][0] = __expf(s[nt][0] - mn0); lt0 += s[nt][0];
                s[nt][1] = __expf(s[nt][1] - mn0); lt0 += s[nt][1];
                s[nt][2] = __expf(s[nt][2] - mn1); lt1 += s[nt][2];
                s[nt][3] = __expf(s[nt][3] - mn1); lt1 += s[nt][3];
            }
            lt0 += __shfl_xor_sync(0xffffffffu, lt0, 1);
            lt0 += __shfl_xor_sync(0xffffffffu, lt0, 2);
            lt1 += __shfl_xor_sync(0xffffffffu, lt1, 1);
            lt1 += __shfl_xor_sync(0xffffffffu, lt1, 2);
            lrun0 = lrun0 * f0 + lt0;
            lrun1 = lrun1 * f1 + lt1;
            #pragma unroll
            for (int nt = 0; nt < 8; nt++) {
                o[nt][0] *= f0; o[nt][1] *= f0;
                o[nt][2] *= f1; o[nt][3] *= f1;
            }

            const uint32_t vaddr = sb + SKV(bfr, 1) + hb * (64 * ASTR) + v_off;
            #pragma unroll
            for (int kt = 0; kt < 4; kt++) {
                uint32_t ap[4];
                ap[0] = pack_h2(s[2 * kt][0],     s[2 * kt][1]);
                ap[1] = pack_h2(s[2 * kt][2],     s[2 * kt][3]);
                ap[2] = pack_h2(s[2 * kt + 1][0], s[2 * kt + 1][1]);
                ap[3] = pack_h2(s[2 * kt + 1][2], s[2 * kt + 1][3]);
                #pragma unroll
                for (int np = 0; np < 4; np++) {
                    uint32_t v0, v1, v2, v3;
                    ldsm_x4_t(v0, v1, v2, v3, vaddr + kt * (16 * ASTR) + np * 32);
                    mma16816(o[2 * np],     ap, v0, v1);
                    mma16816(o[2 * np + 1], ap, v2, v3);
                }
            }
        }
    }

    const float inv0 = 1.0f / lrun0;
    const float inv1 = 1.0f / lrun1;
    const size_t r0 = (size_t)bb * SEQ + q0 + wm0 + g;
    const int colb = h * HDIM + t2;
    #pragma unroll
    for (int nt = 0; nt < 8; nt++) {
        *(uint32_t*)&g_ao_h[r0 * DMODEL + colb + nt * 8] =
            pack_h2(o[nt][0] * inv0, o[nt][1] * inv0);
        *(uint32_t*)&g_ao_h[(r0 + 8) * DMODEL + colb + nt * 8] =
            pack_h2(o[nt][2] * inv1, o[nt][3] * inv1);
    }
}

// ---------------------------------------------------------------------------
extern "C" void kernel_launch(void* const* d_in, const int* in_sizes, int n_in,
                              void* d_out, int out_size)
{
    const float* x      = (const float*)d_in[0];
    const float* w_attn = (const float*)d_in[1];
    const float* b_attn = (const float*)d_in[2];
    const float* w_proj = (const float*)d_in[3];
    const float* b_proj = (const float*)d_in[4];
    float* out = (float*)d_out;

    cudaFuncSetAttribute(attn_mma,
                         cudaFuncAttributeMaxDynamicSharedMemorySize, ATT_SMEM);
    cudaFuncSetAttribute(gemm_qkv_mma,
                         cudaFuncAttributeMaxDynamicSharedMemorySize, GSMEM);
    cudaFuncSetAttribute(gemm_proj_mma,
                         cudaFuncAttributeMaxDynamicSharedMemorySize, GSMEM);

    conv_all<<<(int)(NTOT / 1024), 256>>>(x, w_attn, w_proj);
    gemm_qkv_mma<<<dim3(3 * DMODEL / 128, MTOT / 128), 256, GSMEM>>>(b_attn);
    attn_mma<<<dim3(SEQ / 128, BATCH * NHEAD), 256, ATT_SMEM>>>();
    gemm_proj_mma<<<dim3(DMODEL / 128, MTOT / 128), 256, GSMEM>>>(b_proj, out);
}